// round 1
// baseline (speedup 1.0000x reference)
#include <cuda_runtime.h>
#include <cuda_bf16.h>
#include <math.h>

// Problem constants (fixed by the reference)
#define BATCH   2
#define SEQ     2048
#define HID     1024
#define NHEADS  16
#define HD      64
#define QKV_N   3072   // 3*HID
#define MROWS   4096   // BATCH*SEQ

// Scratch (device globals — no allocations allowed)
__device__ float g_qkv[(size_t)BATCH * SEQ * QKV_N];   // (b, s, 3H)
__device__ float g_attn[(size_t)BATCH * SEQ * HID];    // (b, s, h, d) == (B,S,H) contiguous

// ---------------------------------------------------------------------------
// SGEMM with fused bias: C[M,N] = A[M,K] @ B[K,N] + bias[N]
// 128x128 tile, BK=8, 256 threads, 8x8 per thread, float4 everywhere.
// Requires M%128==0, N%128==0, K%8==0 (true for all our shapes).
// ---------------------------------------------------------------------------
__global__ __launch_bounds__(256) void sgemm_bias_kernel(
    const float* __restrict__ A, const float* __restrict__ B,
    const float* __restrict__ bias, float* __restrict__ C,
    int M, int N, int K)
{
    __shared__ float As[8][128];
    __shared__ float Bs[8][128];

    const int tid = threadIdx.x;
    const int block_row = blockIdx.y * 128;
    const int block_col = blockIdx.x * 128;

    const int tx = tid & 15;        // 0..15 -> column group
    const int ty = tid >> 4;        // 0..15 -> row group

    // Global->shared load mapping
    const int a_row  = tid >> 1;          // 0..127
    const int a_col4 = (tid & 1) * 4;     // 0 or 4
    const int b_row  = tid >> 5;          // 0..7
    const int b_col4 = (tid & 31) * 4;    // 0..124

    const float* Aptr = A + (size_t)block_row * K;
    const float* Bptr = B + block_col;

    float acc[8][8];
#pragma unroll
    for (int i = 0; i < 8; i++)
#pragma unroll
        for (int j = 0; j < 8; j++) acc[i][j] = 0.0f;

    for (int k0 = 0; k0 < K; k0 += 8) {
        float4 av = *(const float4*)(Aptr + (size_t)a_row * K + k0 + a_col4);
        As[a_col4 + 0][a_row] = av.x;
        As[a_col4 + 1][a_row] = av.y;
        As[a_col4 + 2][a_row] = av.z;
        As[a_col4 + 3][a_row] = av.w;
        *(float4*)&Bs[b_row][b_col4] =
            *(const float4*)(Bptr + (size_t)(k0 + b_row) * N + b_col4);
        __syncthreads();

#pragma unroll
        for (int kk = 0; kk < 8; kk++) {
            float ar[8], br[8];
            *(float4*)&ar[0] = *(const float4*)&As[kk][ty * 8];
            *(float4*)&ar[4] = *(const float4*)&As[kk][ty * 8 + 4];
            *(float4*)&br[0] = *(const float4*)&Bs[kk][tx * 8];
            *(float4*)&br[4] = *(const float4*)&Bs[kk][tx * 8 + 4];
#pragma unroll
            for (int i = 0; i < 8; i++)
#pragma unroll
                for (int j = 0; j < 8; j++)
                    acc[i][j] += ar[i] * br[j];
        }
        __syncthreads();
    }

#pragma unroll
    for (int i = 0; i < 8; i++) {
        const int row = block_row + ty * 8 + i;
#pragma unroll
        for (int j = 0; j < 8; j += 4) {
            const int col = block_col + tx * 8 + j;
            float4 bv = *(const float4*)(bias + col);
            float4 o;
            o.x = acc[i][j + 0] + bv.x;
            o.y = acc[i][j + 1] + bv.y;
            o.z = acc[i][j + 2] + bv.z;
            o.w = acc[i][j + 3] + bv.w;
            *(float4*)(C + (size_t)row * N + col) = o;
        }
    }
}

// ---------------------------------------------------------------------------
// Causal flash attention, fp32. One thread per query row (128 q-rows / block).
// K/V tiles of 64 rows live in shared memory; inner reads are warp-uniform
// (broadcast, conflict-free). Online softmax with rare-rescale branch.
// Writes output in (b, s, h, d) layout == (B,S,HID) contiguous.
// ---------------------------------------------------------------------------
__global__ __launch_bounds__(128) void attn_kernel(
    const float* __restrict__ qkv, float* __restrict__ out)
{
    __shared__ float4 Ks[64 * 16];   // 64 keys x 64 floats
    __shared__ float4 Vs[64 * 16];

    const int t    = threadIdx.x;
    const int qblk = blockIdx.x;              // 16 blocks of 128 queries
    const int bh   = blockIdx.y;              // 32 = B*NHEADS
    const int b    = bh >> 4;
    const int h    = bh & 15;
    const int q_row = qblk * 128 + t;

    const float* base = qkv + (size_t)b * SEQ * QKV_N;
    const float* qptr = base + (size_t)q_row * QKV_N + h * HD;
    const float* Kbase = base + HID     + (size_t)h * HD;
    const float* Vbase = base + 2 * HID + (size_t)h * HD;

    // Load q, pre-scaled by 1/sqrt(hd) = 0.125
    float4 q[16];
#pragma unroll
    for (int i = 0; i < 16; i++) {
        float4 v = ((const float4*)qptr)[i];
        v.x *= 0.125f; v.y *= 0.125f; v.z *= 0.125f; v.w *= 0.125f;
        q[i] = v;
    }

    float m = -1e30f;
    float l = 0.0f;
    float acc[64];
#pragma unroll
    for (int d = 0; d < 64; d++) acc[d] = 0.0f;

    const int kmax = qblk * 128 + 128;   // causal: no key beyond block's last query

    for (int k0 = 0; k0 < kmax; k0 += 64) {
        __syncthreads();
        // Cooperative tile load: 1024 float4 per tensor, 8 per thread.
#pragma unroll
        for (int i = 0; i < 8; i++) {
            const int f = i * 128 + t;
            const int r = f >> 4;
            const int c = f & 15;
            Ks[f] = ((const float4*)(Kbase + (size_t)(k0 + r) * QKV_N))[c];
            Vs[f] = ((const float4*)(Vbase + (size_t)(k0 + r) * QKV_N))[c];
        }
        __syncthreads();

        const int jlim = min(64, q_row - k0 + 1);   // causal mask inside tile
        for (int j = 0; j < jlim; j++) {
            const float4* kr = &Ks[j * 16];
            float s0 = 0.f, s1 = 0.f, s2 = 0.f, s3 = 0.f;
#pragma unroll
            for (int d = 0; d < 16; d++) {
                float4 kk = kr[d];
                s0 += q[d].x * kk.x;
                s1 += q[d].y * kk.y;
                s2 += q[d].z * kk.z;
                s3 += q[d].w * kk.w;
            }
            const float s = (s0 + s1) + (s2 + s3);

            float p;
            if (s > m) {
                const float c = __expf(m - s);
                m = s;
                l *= c;
#pragma unroll
                for (int d = 0; d < 64; d++) acc[d] *= c;
                p = 1.0f;
            } else {
                p = __expf(s - m);
            }
            l += p;

            const float4* vr = &Vs[j * 16];
#pragma unroll
            for (int d = 0; d < 16; d++) {
                float4 vv = vr[d];
                acc[4 * d + 0] += p * vv.x;
                acc[4 * d + 1] += p * vv.y;
                acc[4 * d + 2] += p * vv.z;
                acc[4 * d + 3] += p * vv.w;
            }
        }
    }

    const float inv = 1.0f / l;
    float* optr = out + ((size_t)(b * SEQ + q_row) * HID) + h * HD;
#pragma unroll
    for (int d = 0; d < 16; d++) {
        float4 o;
        o.x = acc[4 * d + 0] * inv;
        o.y = acc[4 * d + 1] * inv;
        o.z = acc[4 * d + 2] * inv;
        o.w = acc[4 * d + 3] * inv;
        ((float4*)optr)[d] = o;
    }
}

// ---------------------------------------------------------------------------
extern "C" void kernel_launch(void* const* d_in, const int* in_sizes, int n_in,
                              void* d_out, int out_size)
{
    const float* x     = (const float*)d_in[0];
    const float* w_qkv = (const float*)d_in[1];
    const float* b_qkv = (const float*)d_in[2];
    const float* w_out = (const float*)d_in[3];
    const float* b_out = (const float*)d_in[4];
    float* out = (float*)d_out;

    float* qkv;
    float* attn;
    cudaGetSymbolAddress((void**)&qkv,  g_qkv);
    cudaGetSymbolAddress((void**)&attn, g_attn);

    // 1) QKV projection: (4096,1024)@(1024,3072)+b -> g_qkv
    {
        dim3 grid(QKV_N / 128, MROWS / 128);
        sgemm_bias_kernel<<<grid, 256>>>(x, w_qkv, b_qkv, qkv, MROWS, QKV_N, HID);
    }
    // 2) Causal attention -> g_attn (in (B,S,H) layout)
    {
        dim3 grid(SEQ / 128, BATCH * NHEADS);
        attn_kernel<<<grid, 128>>>(qkv, attn);
    }
    // 3) Output projection: (4096,1024)@(1024,1024)+b -> d_out
    {
        dim3 grid(HID / 128, MROWS / 128);
        sgemm_bias_kernel<<<grid, 256>>>(attn, w_out, b_out, out, MROWS, HID, HID);
    }
}

// round 3
// speedup vs baseline: 1.3892x; 1.3892x over previous
#include <cuda_runtime.h>
#include <cuda_bf16.h>
#include <cstdint>
#include <math.h>

// Problem constants
#define BATCH   2
#define SEQ     2048
#define HID     1024
#define NHEADS  16
#define HD      64
#define QKV_N   3072
#define MROWS   4096
#define KS      3072          // stacked K = 3*1024

// ---------------- scratch (device globals; no allocations allowed) ----------
__device__ float g_qkv[(size_t)MROWS * QKV_N];                 // (b,s,3H) fp32
__device__ float g_attn[(size_t)MROWS * HID];                  // (b,s,H) fp32
__device__ __nv_bfloat16 g_as[(size_t)MROWS * KS];             // stacked activations [hi,lo,hi]
__device__ __nv_bfloat16 g_wqkv_s[(size_t)QKV_N * KS];         // stacked W^T [hi,hi,lo]
__device__ __nv_bfloat16 g_wout_s[(size_t)HID * KS];

// ---------------- PTX helpers (base ISA only — no tcgen05 on compute_103) ---
__device__ __forceinline__ uint32_t smem_u32(const void* p) {
    uint32_t a;
    asm("{ .reg .u64 t; cvta.to.shared.u64 t, %1; cvt.u32.u64 %0, t; }" : "=r"(a) : "l"(p));
    return a;
}

__device__ __forceinline__ void cp_async16(uint32_t s, const void* g) {
    asm volatile("cp.async.cg.shared.global [%0], [%1], 16;" :: "r"(s), "l"(g) : "memory");
}
#define CP_COMMIT() asm volatile("cp.async.commit_group;" ::: "memory")
#define CP_WAIT1()  asm volatile("cp.async.wait_group 1;"  ::: "memory")

#define LDSM_X4(R0, R1, R2, R3, ADDR)                                          \
    asm volatile("ldmatrix.sync.aligned.m8n8.x4.shared.b16 {%0,%1,%2,%3}, [%4];" \
                 : "=r"(R0), "=r"(R1), "=r"(R2), "=r"(R3) : "r"(ADDR))

#define MMA16816(D, A, B0, B1)                                                 \
    asm volatile("mma.sync.aligned.m16n8k16.row.col.f32.bf16.bf16.f32 "        \
                 "{%0,%1,%2,%3},{%4,%5,%6,%7},{%8,%9},{%0,%1,%2,%3};"          \
                 : "+f"((D)[0]), "+f"((D)[1]), "+f"((D)[2]), "+f"((D)[3])      \
                 : "r"((A)[0]), "r"((A)[1]), "r"((A)[2]), "r"((A)[3]),         \
                   "r"(B0), "r"(B1))

// ---------------------------------------------------------------------------
// Conversion: fp32 activations [R,1024] -> stacked bf16 [R,3072] = [hi | lo | hi]
// ---------------------------------------------------------------------------
__global__ __launch_bounds__(256) void convert_act_kernel(
    const float* __restrict__ in, __nv_bfloat16* __restrict__ out, int R)
{
    int idx = blockIdx.x * 256 + threadIdx.x;
    int total = R * 1024;
    if (idx >= total) return;
    int m = idx >> 10;
    int k = idx & 1023;
    float v = in[idx];
    __nv_bfloat16 h = __float2bfloat16(v);
    __nv_bfloat16 l = __float2bfloat16(v - __bfloat162float(h));
    size_t o = (size_t)m * KS + k;
    out[o]        = h;
    out[o + 1024] = l;
    out[o + 2048] = h;
}

// ---------------------------------------------------------------------------
// Conversion + transpose: W fp32 [K=1024, N] -> stacked bf16 [N,3072] = [hi|hi|lo]
// ---------------------------------------------------------------------------
__global__ __launch_bounds__(1024) void convert_w_kernel(
    const float* __restrict__ w, __nv_bfloat16* __restrict__ out, int N)
{
    __shared__ float tile[32][33];
    int tx = threadIdx.x & 31;
    int ty = threadIdx.x >> 5;
    int gn = blockIdx.x * 32;
    int gk = blockIdx.y * 32;
    tile[ty][tx] = w[(size_t)(gk + ty) * N + gn + tx];
    __syncthreads();
    float v = tile[tx][ty];     // element (k = gk+tx, n = gn+ty)
    __nv_bfloat16 h = __float2bfloat16(v);
    __nv_bfloat16 l = __float2bfloat16(v - __bfloat162float(h));
    size_t o = (size_t)(gn + ty) * KS + gk + tx;
    out[o]        = h;
    out[o + 1024] = h;
    out[o + 2048] = l;
}

// ---------------------------------------------------------------------------
// HMMA GEMM: C[M,N] = As[M,3072] @ Bs[N,3072]^T + bias (fp32 accum).
// 128x128x64 CTA tile, 256 threads (8 warps, 2x4), warp tile 64x32.
// 3-stage cp.async pipeline; 128B rows with XOR-16B swizzle; ldmatrix-fed
// mma.sync.m16n8k16 bf16.
// ---------------------------------------------------------------------------
#define BM 128
#define BN 128
#define BK 64
#define NKITER (KS / BK)                   // 48
#define TILE_A_BYTES (BM * 128)            // 16 KB (128 rows x 64 bf16)
#define TILE_B_BYTES (BN * 128)
#define STAGE_BYTES  (TILE_A_BYTES + TILE_B_BYTES)
#define GEMM_SMEM    (3 * STAGE_BYTES + 128)

__global__ __launch_bounds__(256) void mma_gemm_kernel(
    const __nv_bfloat16* __restrict__ As, const __nv_bfloat16* __restrict__ Bs,
    const float* __restrict__ bias, float* __restrict__ C, int M, int N)
{
    extern __shared__ char dsmem[];
    const uint32_t smem_base = (smem_u32(dsmem) + 127u) & ~127u;

    const int tid  = threadIdx.x;
    const int wid  = tid >> 5;
    const int lane = tid & 31;
    const int wm   = wid >> 2;     // 0..1  (64-row slabs)
    const int wn   = wid & 3;      // 0..3  (32-col slabs)

    const int block_row = blockIdx.y * BM;
    const int block_col = blockIdx.x * BN;

    const __nv_bfloat16* Abase = As + (size_t)block_row * KS;
    const __nv_bfloat16* Bbase = Bs + (size_t)block_col * KS;

    // ---- stage fill: 1024 x 16B segments per tensor, 4 per thread ----
    auto load_stage = [&](int stage, int kc) {
        const uint32_t sA = smem_base + stage * STAGE_BYTES;
        const uint32_t sB = sA + TILE_A_BYTES;
#pragma unroll
        for (int i = 0; i < 4; i++) {
            const int s   = i * 256 + tid;
            const int row = s >> 3;
            const int ch  = s & 7;
            const uint32_t sw = (uint32_t)(ch * 16) ^ (uint32_t)((row & 7) << 4);
            cp_async16(sA + row * 128 + sw, Abase + (size_t)row * KS + kc + ch * 8);
            cp_async16(sB + row * 128 + sw, Bbase + (size_t)row * KS + kc + ch * 8);
        }
        CP_COMMIT();
    };

    float acc[4][4][4];
#pragma unroll
    for (int mt = 0; mt < 4; mt++)
#pragma unroll
        for (int nt = 0; nt < 4; nt++)
#pragma unroll
            for (int r = 0; r < 4; r++) acc[mt][nt][r] = 0.0f;

    load_stage(0, 0);
    load_stage(1, BK);

    // ldmatrix lane addressing (tile-relative): row = lane&15, kseg = lane>>4
    const int lrow  = lane & 15;
    const int kseg  = (lane >> 4) * 16;          // byte offset of k-half
    const uint32_t arow_off = (uint32_t)(wm * 64 + lrow) * 128;
    const uint32_t brow_off = (uint32_t)(wn * 32 + lrow) * 128;
    const uint32_t aswz = (uint32_t)((lrow & 7) << 4);

    for (int it = 0; it < NKITER; it++) {
        CP_WAIT1();
        __syncthreads();
        if (it + 2 < NKITER) load_stage((it + 2) % 3, (it + 2) * BK);
        else                 CP_COMMIT();        // keep group accounting uniform

        const uint32_t sA = smem_base + (it % 3) * STAGE_BYTES;
        const uint32_t sB = sA + TILE_A_BYTES;

#pragma unroll
        for (int kt = 0; kt < 4; kt++) {
            const uint32_t koff = (uint32_t)(kt * 32 + kseg);
            uint32_t a[4][4], b[2][4];
#pragma unroll
            for (int mt = 0; mt < 4; mt++) {
                const uint32_t addr = sA + arow_off + (uint32_t)(mt * 16 * 128)
                                    + (koff ^ aswz);
                LDSM_X4(a[mt][0], a[mt][1], a[mt][2], a[mt][3], addr);
            }
#pragma unroll
            for (int pr = 0; pr < 2; pr++) {
                const uint32_t addr = sB + brow_off + (uint32_t)(pr * 16 * 128)
                                    + (koff ^ aswz);
                LDSM_X4(b[pr][0], b[pr][1], b[pr][2], b[pr][3], addr);
            }
#pragma unroll
            for (int mt = 0; mt < 4; mt++)
#pragma unroll
                for (int nt = 0; nt < 4; nt++) {
                    const int pr = nt >> 1, sub = nt & 1;
                    MMA16816(acc[mt][nt], a[mt], b[pr][sub], b[pr][sub + 2]);
                }
        }
        __syncthreads();
    }

    // ---- epilogue: fused bias, float2 stores ----
    const int rbase = block_row + wm * 64 + (lane >> 2);
    const int cbase = block_col + wn * 32 + (lane & 3) * 2;
#pragma unroll
    for (int mt = 0; mt < 4; mt++) {
#pragma unroll
        for (int nt = 0; nt < 4; nt++) {
            const int col = cbase + nt * 8;
            const float bx = bias[col];
            const float by = bias[col + 1];
            const int r0 = rbase + mt * 16;
            float2 o0 = { acc[mt][nt][0] + bx, acc[mt][nt][1] + by };
            float2 o1 = { acc[mt][nt][2] + bx, acc[mt][nt][3] + by };
            *(float2*)(C + (size_t)r0 * N + col)       = o0;
            *(float2*)(C + (size_t)(r0 + 8) * N + col) = o1;
        }
    }
}

// ---------------------------------------------------------------------------
// Causal flash attention, fp32 (unchanged). 1 thread = 1 query row.
// ---------------------------------------------------------------------------
__global__ __launch_bounds__(128) void attn_kernel(
    const float* __restrict__ qkv, float* __restrict__ out)
{
    __shared__ float4 Ks[64 * 16];
    __shared__ float4 Vs[64 * 16];

    const int t    = threadIdx.x;
    const int qblk = blockIdx.x;
    const int bh   = blockIdx.y;
    const int b    = bh >> 4;
    const int h    = bh & 15;
    const int q_row = qblk * 128 + t;

    const float* base = qkv + (size_t)b * SEQ * QKV_N;
    const float* qptr = base + (size_t)q_row * QKV_N + h * HD;
    const float* Kbase = base + HID     + (size_t)h * HD;
    const float* Vbase = base + 2 * HID + (size_t)h * HD;

    float4 q[16];
#pragma unroll
    for (int i = 0; i < 16; i++) {
        float4 v = ((const float4*)qptr)[i];
        v.x *= 0.125f; v.y *= 0.125f; v.z *= 0.125f; v.w *= 0.125f;
        q[i] = v;
    }

    float m = -1e30f;
    float l = 0.0f;
    float acc[64];
#pragma unroll
    for (int d = 0; d < 64; d++) acc[d] = 0.0f;

    const int kmax = qblk * 128 + 128;

    for (int k0 = 0; k0 < kmax; k0 += 64) {
        __syncthreads();
#pragma unroll
        for (int i = 0; i < 8; i++) {
            const int f = i * 128 + t;
            const int r = f >> 4;
            const int c = f & 15;
            Ks[f] = ((const float4*)(Kbase + (size_t)(k0 + r) * QKV_N))[c];
            Vs[f] = ((const float4*)(Vbase + (size_t)(k0 + r) * QKV_N))[c];
        }
        __syncthreads();

        const int jlim = min(64, q_row - k0 + 1);
        for (int j = 0; j < jlim; j++) {
            const float4* kr = &Ks[j * 16];
            float s0 = 0.f, s1 = 0.f, s2 = 0.f, s3 = 0.f;
#pragma unroll
            for (int d = 0; d < 16; d++) {
                float4 kk = kr[d];
                s0 += q[d].x * kk.x;
                s1 += q[d].y * kk.y;
                s2 += q[d].z * kk.z;
                s3 += q[d].w * kk.w;
            }
            const float s = (s0 + s1) + (s2 + s3);

            float p;
            if (s > m) {
                const float cc = __expf(m - s);
                m = s;
                l *= cc;
#pragma unroll
                for (int d = 0; d < 64; d++) acc[d] *= cc;
                p = 1.0f;
            } else {
                p = __expf(s - m);
            }
            l += p;

            const float4* vr = &Vs[j * 16];
#pragma unroll
            for (int d = 0; d < 16; d++) {
                float4 vv = vr[d];
                acc[4 * d + 0] += p * vv.x;
                acc[4 * d + 1] += p * vv.y;
                acc[4 * d + 2] += p * vv.z;
                acc[4 * d + 3] += p * vv.w;
            }
        }
    }

    const float inv = 1.0f / l;
    float* optr = out + ((size_t)(b * SEQ + q_row) * HID) + h * HD;
#pragma unroll
    for (int d = 0; d < 16; d++) {
        float4 o;
        o.x = acc[4 * d + 0] * inv;
        o.y = acc[4 * d + 1] * inv;
        o.z = acc[4 * d + 2] * inv;
        o.w = acc[4 * d + 3] * inv;
        ((float4*)optr)[d] = o;
    }
}

// ---------------------------------------------------------------------------
extern "C" void kernel_launch(void* const* d_in, const int* in_sizes, int n_in,
                              void* d_out, int out_size)
{
    const float* x     = (const float*)d_in[0];
    const float* w_qkv = (const float*)d_in[1];
    const float* b_qkv = (const float*)d_in[2];
    const float* w_out = (const float*)d_in[3];
    const float* b_out = (const float*)d_in[4];
    float* out = (float*)d_out;

    float *qkv, *attn;
    __nv_bfloat16 *as, *wqkvs, *wouts;
    cudaGetSymbolAddress((void**)&qkv,   g_qkv);
    cudaGetSymbolAddress((void**)&attn,  g_attn);
    cudaGetSymbolAddress((void**)&as,    g_as);
    cudaGetSymbolAddress((void**)&wqkvs, g_wqkv_s);
    cudaGetSymbolAddress((void**)&wouts, g_wout_s);

    cudaFuncSetAttribute(mma_gemm_kernel,
                         cudaFuncAttributeMaxDynamicSharedMemorySize, GEMM_SMEM);

    // 1) Convert weights (transpose + hi/lo split)
    {
        dim3 grid(QKV_N / 32, HID / 32);
        convert_w_kernel<<<grid, 1024>>>(w_qkv, wqkvs, QKV_N);
    }
    {
        dim3 grid(HID / 32, HID / 32);
        convert_w_kernel<<<grid, 1024>>>(w_out, wouts, HID);
    }
    // 2) Convert x
    convert_act_kernel<<<(MROWS * 1024 + 255) / 256, 256>>>(x, as, MROWS);
    // 3) QKV projection (HMMA tensor cores)
    {
        dim3 grid(QKV_N / BN, MROWS / BM);
        mma_gemm_kernel<<<grid, 256, GEMM_SMEM>>>(as, wqkvs, b_qkv, qkv, MROWS, QKV_N);
    }
    // 4) Attention
    {
        dim3 grid(SEQ / 128, BATCH * NHEADS);
        attn_kernel<<<grid, 128>>>(qkv, attn);
    }
    // 5) Convert attention output
    convert_act_kernel<<<(MROWS * 1024 + 255) / 256, 256>>>(attn, as, MROWS);
    // 6) Output projection (HMMA tensor cores)
    {
        dim3 grid(HID / BN, MROWS / BM);
        mma_gemm_kernel<<<grid, 256, GEMM_SMEM>>>(as, wouts, b_out, out, MROWS, HID);
    }
}

// round 4
// speedup vs baseline: 2.5494x; 1.8351x over previous
#include <cuda_runtime.h>
#include <cuda_bf16.h>
#include <cstdint>
#include <math.h>

// Problem constants
#define BATCH   2
#define SEQ     2048
#define HID     1024
#define NHEADS  16
#define HD      64
#define QKV_N   3072
#define MROWS   4096
#define KS      3072          // stacked K = 3*1024

// ---------------- scratch (device globals; no allocations allowed) ----------
__device__ float g_qkv[(size_t)MROWS * QKV_N];                 // (b,s,3H) fp32
__device__ __nv_bfloat16 g_as[(size_t)MROWS * KS];             // stacked activations [hi,lo,hi]
__device__ __nv_bfloat16 g_wqkv_s[(size_t)QKV_N * KS];         // stacked W^T [hi,hi,lo]
__device__ __nv_bfloat16 g_wout_s[(size_t)HID * KS];

// ---------------- PTX helpers (base ISA only) ----------------
__device__ __forceinline__ uint32_t smem_u32(const void* p) {
    uint32_t a;
    asm("{ .reg .u64 t; cvta.to.shared.u64 t, %1; cvt.u32.u64 %0, t; }" : "=r"(a) : "l"(p));
    return a;
}

__device__ __forceinline__ void cp_async16(uint32_t s, const void* g) {
    asm volatile("cp.async.cg.shared.global [%0], [%1], 16;" :: "r"(s), "l"(g) : "memory");
}
#define CP_COMMIT() asm volatile("cp.async.commit_group;" ::: "memory")
#define CP_WAIT1()  asm volatile("cp.async.wait_group 1;"  ::: "memory")

#define LDSM_X4(R0, R1, R2, R3, ADDR)                                          \
    asm volatile("ldmatrix.sync.aligned.m8n8.x4.shared.b16 {%0,%1,%2,%3}, [%4];" \
                 : "=r"(R0), "=r"(R1), "=r"(R2), "=r"(R3) : "r"(ADDR))

#define LDSM_X4T(R0, R1, R2, R3, ADDR)                                         \
    asm volatile("ldmatrix.sync.aligned.m8n8.x4.trans.shared.b16 {%0,%1,%2,%3}, [%4];" \
                 : "=r"(R0), "=r"(R1), "=r"(R2), "=r"(R3) : "r"(ADDR))

#define MMA16816(D, A, B0, B1)                                                 \
    asm volatile("mma.sync.aligned.m16n8k16.row.col.f32.bf16.bf16.f32 "        \
                 "{%0,%1,%2,%3},{%4,%5,%6,%7},{%8,%9},{%0,%1,%2,%3};"          \
                 : "+f"((D)[0]), "+f"((D)[1]), "+f"((D)[2]), "+f"((D)[3])      \
                 : "r"((A)[0]), "r"((A)[1]), "r"((A)[2]), "r"((A)[3]),         \
                   "r"(B0), "r"(B1))

// Fast exp2 on the FMA/ALU pipes (no MUFU). x <= 0 expected; rel err ~1e-7.
__device__ __forceinline__ float fexp2(float x) {
    x = fmaxf(x, -125.0f);
    int   n  = __float2int_rn(x);
    float f  = x - (float)n;                 // f in [-0.5, 0.5]
    float p  = 1.535336188319500e-4f;
    p = fmaf(p, f, 1.339887440266574e-3f);
    p = fmaf(p, f, 9.618437357674640e-3f);
    p = fmaf(p, f, 5.550332471162809e-2f);
    p = fmaf(p, f, 2.402264791363012e-1f);
    p = fmaf(p, f, 6.931472028550421e-1f);
    p = fmaf(p, f, 1.0f);
    return __int_as_float(__float_as_int(p) + (n << 23));
}

__device__ __forceinline__ uint32_t packbf2(__nv_bfloat16 a, __nv_bfloat16 b) {
    __nv_bfloat162 t;
    t.x = a; t.y = b;
    return *reinterpret_cast<uint32_t*>(&t);
}

// ---------------------------------------------------------------------------
// Conversion: fp32 activations [R,1024] -> stacked bf16 [R,3072] = [hi | lo | hi]
// ---------------------------------------------------------------------------
__global__ __launch_bounds__(256) void convert_act_kernel(
    const float* __restrict__ in, __nv_bfloat16* __restrict__ out, int R)
{
    int idx = blockIdx.x * 256 + threadIdx.x;
    int total = R * 1024;
    if (idx >= total) return;
    int m = idx >> 10;
    int k = idx & 1023;
    float v = in[idx];
    __nv_bfloat16 h = __float2bfloat16(v);
    __nv_bfloat16 l = __float2bfloat16(v - __bfloat162float(h));
    size_t o = (size_t)m * KS + k;
    out[o]        = h;
    out[o + 1024] = l;
    out[o + 2048] = h;
}

// ---------------------------------------------------------------------------
// Conversion + transpose: W fp32 [K=1024, N] -> stacked bf16 [N,3072] = [hi|hi|lo]
// ---------------------------------------------------------------------------
__global__ __launch_bounds__(1024) void convert_w_kernel(
    const float* __restrict__ w, __nv_bfloat16* __restrict__ out, int N)
{
    __shared__ float tile[32][33];
    int tx = threadIdx.x & 31;
    int ty = threadIdx.x >> 5;
    int gn = blockIdx.x * 32;
    int gk = blockIdx.y * 32;
    tile[ty][tx] = w[(size_t)(gk + ty) * N + gn + tx];
    __syncthreads();
    float v = tile[tx][ty];
    __nv_bfloat16 h = __float2bfloat16(v);
    __nv_bfloat16 l = __float2bfloat16(v - __bfloat162float(h));
    size_t o = (size_t)(gn + ty) * KS + gk + tx;
    out[o]        = h;
    out[o + 1024] = h;
    out[o + 2048] = l;
}

// ---------------------------------------------------------------------------
// HMMA GEMM (unchanged from R3): C[M,N] = As[M,3072] @ Bs[N,3072]^T + bias.
// ---------------------------------------------------------------------------
#define BM 128
#define BN 128
#define BK 64
#define NKITER (KS / BK)
#define TILE_A_BYTES (BM * 128)
#define TILE_B_BYTES (BN * 128)
#define STAGE_BYTES  (TILE_A_BYTES + TILE_B_BYTES)
#define GEMM_SMEM    (3 * STAGE_BYTES + 128)

__global__ __launch_bounds__(256) void mma_gemm_kernel(
    const __nv_bfloat16* __restrict__ As, const __nv_bfloat16* __restrict__ Bs,
    const float* __restrict__ bias, float* __restrict__ C, int M, int N)
{
    extern __shared__ char dsmem[];
    const uint32_t smem_base = (smem_u32(dsmem) + 127u) & ~127u;

    const int tid  = threadIdx.x;
    const int wid  = tid >> 5;
    const int lane = tid & 31;
    const int wm   = wid >> 2;
    const int wn   = wid & 3;

    const int block_row = blockIdx.y * BM;
    const int block_col = blockIdx.x * BN;

    const __nv_bfloat16* Abase = As + (size_t)block_row * KS;
    const __nv_bfloat16* Bbase = Bs + (size_t)block_col * KS;

    auto load_stage = [&](int stage, int kc) {
        const uint32_t sA = smem_base + stage * STAGE_BYTES;
        const uint32_t sB = sA + TILE_A_BYTES;
#pragma unroll
        for (int i = 0; i < 4; i++) {
            const int s   = i * 256 + tid;
            const int row = s >> 3;
            const int ch  = s & 7;
            const uint32_t sw = (uint32_t)(ch * 16) ^ (uint32_t)((row & 7) << 4);
            cp_async16(sA + row * 128 + sw, Abase + (size_t)row * KS + kc + ch * 8);
            cp_async16(sB + row * 128 + sw, Bbase + (size_t)row * KS + kc + ch * 8);
        }
        CP_COMMIT();
    };

    float acc[4][4][4];
#pragma unroll
    for (int mt = 0; mt < 4; mt++)
#pragma unroll
        for (int nt = 0; nt < 4; nt++)
#pragma unroll
            for (int r = 0; r < 4; r++) acc[mt][nt][r] = 0.0f;

    load_stage(0, 0);
    load_stage(1, BK);

    const int lrow  = lane & 15;
    const int kseg  = (lane >> 4) * 16;
    const uint32_t arow_off = (uint32_t)(wm * 64 + lrow) * 128;
    const uint32_t brow_off = (uint32_t)(wn * 32 + lrow) * 128;
    const uint32_t aswz = (uint32_t)((lrow & 7) << 4);

    for (int it = 0; it < NKITER; it++) {
        CP_WAIT1();
        __syncthreads();
        if (it + 2 < NKITER) load_stage((it + 2) % 3, (it + 2) * BK);
        else                 CP_COMMIT();

        const uint32_t sA = smem_base + (it % 3) * STAGE_BYTES;
        const uint32_t sB = sA + TILE_A_BYTES;

#pragma unroll
        for (int kt = 0; kt < 4; kt++) {
            const uint32_t koff = (uint32_t)(kt * 32 + kseg);
            uint32_t a[4][4], b[2][4];
#pragma unroll
            for (int mt = 0; mt < 4; mt++) {
                const uint32_t addr = sA + arow_off + (uint32_t)(mt * 16 * 128)
                                    + (koff ^ aswz);
                LDSM_X4(a[mt][0], a[mt][1], a[mt][2], a[mt][3], addr);
            }
#pragma unroll
            for (int pr = 0; pr < 2; pr++) {
                const uint32_t addr = sB + brow_off + (uint32_t)(pr * 16 * 128)
                                    + (koff ^ aswz);
                LDSM_X4(b[pr][0], b[pr][1], b[pr][2], b[pr][3], addr);
            }
#pragma unroll
            for (int mt = 0; mt < 4; mt++)
#pragma unroll
                for (int nt = 0; nt < 4; nt++) {
                    const int pr = nt >> 1, sub = nt & 1;
                    MMA16816(acc[mt][nt], a[mt], b[pr][sub], b[pr][sub + 2]);
                }
        }
        __syncthreads();
    }

    const int rbase = block_row + wm * 64 + (lane >> 2);
    const int cbase = block_col + wn * 32 + (lane & 3) * 2;
#pragma unroll
    for (int mt = 0; mt < 4; mt++) {
#pragma unroll
        for (int nt = 0; nt < 4; nt++) {
            const int col = cbase + nt * 8;
            const float bx = bias[col];
            const float by = bias[col + 1];
            const int r0 = rbase + mt * 16;
            float2 o0 = { acc[mt][nt][0] + bx, acc[mt][nt][1] + by };
            float2 o1 = { acc[mt][nt][2] + bx, acc[mt][nt][3] + by };
            *(float2*)(C + (size_t)r0 * N + col)       = o0;
            *(float2*)(C + (size_t)(r0 + 8) * N + col) = o1;
        }
    }
}

// ---------------------------------------------------------------------------
// HMMA causal flash attention. One CTA = 128 queries of one (b,h).
// 8 warps x 16 query rows. 64-key tiles. bf16 hi/lo 3-pass MMAs for QK^T and
// PV; fp32 online softmax in fragment registers with polynomial exp2.
// Output written directly as stacked bf16 [hi|lo|hi] rows of g_as.
// smem: QH 16K | QL 16K | KH 8K | KL 8K | VH 8K | VL 8K = 64KB
// ---------------------------------------------------------------------------
#define ATTN_SMEM 65536

__global__ __launch_bounds__(256) void attn_mma_kernel(
    const float* __restrict__ qkv, __nv_bfloat16* __restrict__ outs)
{
    extern __shared__ char sm[];
    const uint32_t base = smem_u32(sm);
    const uint32_t sQH = base;
    const uint32_t sQL = base + 16384;
    const uint32_t sKH = base + 32768;
    const uint32_t sKL = base + 40960;
    const uint32_t sVH = base + 49152;
    const uint32_t sVL = base + 57344;

    const int tid  = threadIdx.x;
    const int lane = tid & 31;
    const int wid  = tid >> 5;
    const int qb   = 15 - (int)blockIdx.x;     // heavy blocks first
    const int bh   = blockIdx.y;
    const int b    = bh >> 4;
    const int h    = bh & 15;

    const float* bptr = qkv + (size_t)b * SEQ * QKV_N;
    const float* Qg = bptr + (size_t)(qb * 128) * QKV_N + h * HD;
    const float* Kg = bptr + HID + h * HD;
    const float* Vg = bptr + 2 * HID + h * HD;

    const float QSC = 0.18033688f;             // 0.125 * log2(e)

    // ---- load Q tile, scale, hi/lo split, swizzled smem store ----
    {
        const int row = tid >> 1;
        const int c0  = (tid & 1) * 8;
        const float4* src = (const float4*)(Qg + (size_t)row * QKV_N) + c0;
        char* qh_p = sm + row * 128;
        char* ql_p = sm + 16384 + row * 128;
#pragma unroll
        for (int i = 0; i < 8; i++) {
            float4 v = src[i];
            v.x *= QSC; v.y *= QSC; v.z *= QSC; v.w *= QSC;
            __nv_bfloat16 hx = __float2bfloat16(v.x);
            __nv_bfloat16 hy = __float2bfloat16(v.y);
            __nv_bfloat16 hz = __float2bfloat16(v.z);
            __nv_bfloat16 hw = __float2bfloat16(v.w);
            uint2 hv = { packbf2(hx, hy), packbf2(hz, hw) };
            uint2 lv = { packbf2(__float2bfloat16(v.x - __bfloat162float(hx)),
                                 __float2bfloat16(v.y - __bfloat162float(hy))),
                         packbf2(__float2bfloat16(v.z - __bfloat162float(hz)),
                                 __float2bfloat16(v.w - __bfloat162float(hw))) };
            uint32_t off = (uint32_t)((c0 + i) * 8);
            uint32_t swo = off ^ (uint32_t)((row & 7) << 4);
            *(uint2*)(qh_p + swo) = hv;
            *(uint2*)(ql_p + swo) = lv;
        }
    }

    float acc_o[8][4];
#pragma unroll
    for (int nt = 0; nt < 8; nt++)
#pragma unroll
        for (int r = 0; r < 4; r++) acc_o[nt][r] = 0.0f;
    float m0 = -1e30f, m1 = -1e30f, l0 = 0.0f, l1 = 0.0f;

    const int r0      = lane >> 2;
    const int qrow_w  = qb * 128 + wid * 16;
    const int qg0     = qrow_w + r0;

    // ldmatrix address pieces
    const int a_r = wid * 16 + (lane & 15);
    const int a_c = (lane >> 4) * 16;
    const uint32_t a_row_off = (uint32_t)(a_r * 128);
    const uint32_t a_sw = (uint32_t)((a_r & 7) << 4);
    const int g      = lane >> 3;
    const int br_off = lane & 7;

    const int nk = (qb + 1) * 2;
    for (int t = 0; t < nk; t++) {
        const int k0 = t * 64;
        __syncthreads();
        // ---- load + convert K/V tile (fp32 -> bf16 hi/lo, swizzled) ----
        {
            const int key  = tid >> 2;
            const int quad = tid & 3;
            const float4* kg = (const float4*)(Kg + (size_t)(k0 + key) * QKV_N) + quad * 4;
            const float4* vg = (const float4*)(Vg + (size_t)(k0 + key) * QKV_N) + quad * 4;
            char* kh_p = sm + 32768 + key * 128;
            char* kl_p = sm + 40960 + key * 128;
            char* vh_p = sm + 49152 + key * 128;
            char* vl_p = sm + 57344 + key * 128;
            const uint32_t rs = (uint32_t)((key & 7) << 4);
#pragma unroll
            for (int i = 0; i < 4; i++) {
                uint32_t off = (uint32_t)(quad * 32 + i * 8);
                uint32_t swo = off ^ rs;
                float4 kv = kg[i];
                __nv_bfloat16 ax = __float2bfloat16(kv.x);
                __nv_bfloat16 ay = __float2bfloat16(kv.y);
                __nv_bfloat16 az = __float2bfloat16(kv.z);
                __nv_bfloat16 aw = __float2bfloat16(kv.w);
                uint2 hv = { packbf2(ax, ay), packbf2(az, aw) };
                uint2 lv = { packbf2(__float2bfloat16(kv.x - __bfloat162float(ax)),
                                     __float2bfloat16(kv.y - __bfloat162float(ay))),
                             packbf2(__float2bfloat16(kv.z - __bfloat162float(az)),
                                     __float2bfloat16(kv.w - __bfloat162float(aw))) };
                *(uint2*)(kh_p + swo) = hv;
                *(uint2*)(kl_p + swo) = lv;

                float4 vv = vg[i];
                ax = __float2bfloat16(vv.x);
                ay = __float2bfloat16(vv.y);
                az = __float2bfloat16(vv.z);
                aw = __float2bfloat16(vv.w);
                uint2 hv2 = { packbf2(ax, ay), packbf2(az, aw) };
                uint2 lv2 = { packbf2(__float2bfloat16(vv.x - __bfloat162float(ax)),
                                      __float2bfloat16(vv.y - __bfloat162float(ay))),
                              packbf2(__float2bfloat16(vv.z - __bfloat162float(az)),
                                      __float2bfloat16(vv.w - __bfloat162float(aw))) };
                *(uint2*)(vh_p + swo) = hv2;
                *(uint2*)(vl_p + swo) = lv2;
            }
        }
        __syncthreads();

        // ---- S = Q K^T with 3-pass hi/lo split ----
        float s[8][4];
#pragma unroll
        for (int nt = 0; nt < 8; nt++)
#pragma unroll
            for (int r = 0; r < 4; r++) s[nt][r] = 0.0f;

#pragma unroll
        for (int kc = 0; kc < 4; kc++) {
            uint32_t qh[4], ql[4];
            const uint32_t qoff = ((uint32_t)(kc * 32 + a_c)) ^ a_sw;
            LDSM_X4(qh[0], qh[1], qh[2], qh[3], sQH + a_row_off + qoff);
            LDSM_X4(ql[0], ql[1], ql[2], ql[3], sQL + a_row_off + qoff);
#pragma unroll
            for (int np = 0; np < 4; np++) {
                const int brow = np * 16 + ((g & 2) << 2) + br_off;
                const uint32_t boff = ((uint32_t)(kc * 32 + ((g & 1) << 4)))
                                    ^ (uint32_t)((brow & 7) << 4);
                const uint32_t rb = (uint32_t)(brow * 128) + boff;
                uint32_t b0, b1, b2, b3;
                LDSM_X4(b0, b1, b2, b3, sKH + rb);
                MMA16816(s[2 * np],     qh, b0, b1);
                MMA16816(s[2 * np + 1], qh, b2, b3);
                MMA16816(s[2 * np],     ql, b0, b1);
                MMA16816(s[2 * np + 1], ql, b2, b3);
                LDSM_X4(b0, b1, b2, b3, sKL + rb);
                MMA16816(s[2 * np],     qh, b0, b1);
                MMA16816(s[2 * np + 1], qh, b2, b3);
            }
        }

        // ---- causal mask (only tiles that cross this warp's diagonal) ----
        if (k0 + 63 > qrow_w) {
#pragma unroll
            for (int nt = 0; nt < 8; nt++) {
                const int kg0 = k0 + nt * 8 + 2 * (lane & 3);
                if (kg0     > qg0)     s[nt][0] = -1e30f;
                if (kg0 + 1 > qg0)     s[nt][1] = -1e30f;
                if (kg0     > qg0 + 8) s[nt][2] = -1e30f;
                if (kg0 + 1 > qg0 + 8) s[nt][3] = -1e30f;
            }
        }

        // ---- online softmax (base-2), fragment layout ----
        float rx0 = -1e30f, rx1 = -1e30f;
#pragma unroll
        for (int nt = 0; nt < 8; nt++) {
            rx0 = fmaxf(rx0, fmaxf(s[nt][0], s[nt][1]));
            rx1 = fmaxf(rx1, fmaxf(s[nt][2], s[nt][3]));
        }
        rx0 = fmaxf(rx0, __shfl_xor_sync(0xffffffffu, rx0, 1));
        rx0 = fmaxf(rx0, __shfl_xor_sync(0xffffffffu, rx0, 2));
        rx1 = fmaxf(rx1, __shfl_xor_sync(0xffffffffu, rx1, 1));
        rx1 = fmaxf(rx1, __shfl_xor_sync(0xffffffffu, rx1, 2));
        const float mn0 = fmaxf(m0, rx0);
        const float mn1 = fmaxf(m1, rx1);
        const float sc0 = fexp2(m0 - mn0);
        const float sc1 = fexp2(m1 - mn1);
        m0 = mn0; m1 = mn1;
        l0 *= sc0; l1 *= sc1;
#pragma unroll
        for (int nt = 0; nt < 8; nt++) {
            acc_o[nt][0] *= sc0; acc_o[nt][1] *= sc0;
            acc_o[nt][2] *= sc1; acc_o[nt][3] *= sc1;
        }

        uint32_t ph[4][4], pl[4][4];
#pragma unroll
        for (int nt = 0; nt < 8; nt++) {
            const float p0 = fexp2(s[nt][0] - m0);
            const float p1 = fexp2(s[nt][1] - m0);
            const float p2 = fexp2(s[nt][2] - m1);
            const float p3 = fexp2(s[nt][3] - m1);
            l0 += p0 + p1;
            l1 += p2 + p3;
            const __nv_bfloat16 h0 = __float2bfloat16(p0);
            const __nv_bfloat16 h1 = __float2bfloat16(p1);
            const __nv_bfloat16 h2 = __float2bfloat16(p2);
            const __nv_bfloat16 h3 = __float2bfloat16(p3);
            const int kc = nt >> 1;
            const int rr = (nt & 1) * 2;
            ph[kc][rr]     = packbf2(h0, h1);
            ph[kc][rr + 1] = packbf2(h2, h3);
            pl[kc][rr]     = packbf2(__float2bfloat16(p0 - __bfloat162float(h0)),
                                     __float2bfloat16(p1 - __bfloat162float(h1)));
            pl[kc][rr + 1] = packbf2(__float2bfloat16(p2 - __bfloat162float(h2)),
                                     __float2bfloat16(p3 - __bfloat162float(h3)));
        }

        // ---- O += P V with 3-pass hi/lo split (ldmatrix.trans for V) ----
#pragma unroll
        for (int kc = 0; kc < 4; kc++) {
#pragma unroll
            for (int np = 0; np < 4; np++) {
                const int vrow = kc * 16 + ((g & 1) << 3) + br_off;
                const uint32_t voff = ((uint32_t)(np * 32 + ((g & 2) << 3)))
                                    ^ (uint32_t)((vrow & 7) << 4);
                const uint32_t rv = (uint32_t)(vrow * 128) + voff;
                uint32_t b0, b1, b2, b3;
                LDSM_X4T(b0, b1, b2, b3, sVH + rv);
                MMA16816(acc_o[2 * np],     ph[kc], b0, b1);
                MMA16816(acc_o[2 * np + 1], ph[kc], b2, b3);
                MMA16816(acc_o[2 * np],     pl[kc], b0, b1);
                MMA16816(acc_o[2 * np + 1], pl[kc], b2, b3);
                LDSM_X4T(b0, b1, b2, b3, sVL + rv);
                MMA16816(acc_o[2 * np],     ph[kc], b0, b1);
                MMA16816(acc_o[2 * np + 1], ph[kc], b2, b3);
            }
        }
    }

    // ---- epilogue: normalize, write stacked bf16 hi/lo rows of g_as ----
    l0 += __shfl_xor_sync(0xffffffffu, l0, 1);
    l0 += __shfl_xor_sync(0xffffffffu, l0, 2);
    l1 += __shfl_xor_sync(0xffffffffu, l1, 1);
    l1 += __shfl_xor_sync(0xffffffffu, l1, 2);
    const float inv0 = 1.0f / l0;
    const float inv1 = 1.0f / l1;

    const size_t row0 = (size_t)(b * SEQ + qg0) * KS;
    const size_t row1 = row0 + 8 * KS;
    const int colbase = h * HD + 2 * (lane & 3);
#pragma unroll
    for (int nt = 0; nt < 8; nt++) {
        const int col = colbase + nt * 8;
        const float v0 = acc_o[nt][0] * inv0;
        const float v1 = acc_o[nt][1] * inv0;
        const float v2 = acc_o[nt][2] * inv1;
        const float v3 = acc_o[nt][3] * inv1;
        const __nv_bfloat16 h0 = __float2bfloat16(v0);
        const __nv_bfloat16 h1 = __float2bfloat16(v1);
        const __nv_bfloat16 h2 = __float2bfloat16(v2);
        const __nv_bfloat16 h3 = __float2bfloat16(v3);
        const uint32_t hi01 = packbf2(h0, h1);
        const uint32_t lo01 = packbf2(__float2bfloat16(v0 - __bfloat162float(h0)),
                                      __float2bfloat16(v1 - __bfloat162float(h1)));
        const uint32_t hi23 = packbf2(h2, h3);
        const uint32_t lo23 = packbf2(__float2bfloat16(v2 - __bfloat162float(h2)),
                                      __float2bfloat16(v3 - __bfloat162float(h3)));
        *(uint32_t*)(outs + row0 + col)        = hi01;
        *(uint32_t*)(outs + row0 + col + 1024) = lo01;
        *(uint32_t*)(outs + row0 + col + 2048) = hi01;
        *(uint32_t*)(outs + row1 + col)        = hi23;
        *(uint32_t*)(outs + row1 + col + 1024) = lo23;
        *(uint32_t*)(outs + row1 + col + 2048) = hi23;
    }
}

// ---------------------------------------------------------------------------
extern "C" void kernel_launch(void* const* d_in, const int* in_sizes, int n_in,
                              void* d_out, int out_size)
{
    const float* x     = (const float*)d_in[0];
    const float* w_qkv = (const float*)d_in[1];
    const float* b_qkv = (const float*)d_in[2];
    const float* w_out = (const float*)d_in[3];
    const float* b_out = (const float*)d_in[4];
    float* out = (float*)d_out;

    float *qkv;
    __nv_bfloat16 *as, *wqkvs, *wouts;
    cudaGetSymbolAddress((void**)&qkv,   g_qkv);
    cudaGetSymbolAddress((void**)&as,    g_as);
    cudaGetSymbolAddress((void**)&wqkvs, g_wqkv_s);
    cudaGetSymbolAddress((void**)&wouts, g_wout_s);

    cudaFuncSetAttribute(mma_gemm_kernel,
                         cudaFuncAttributeMaxDynamicSharedMemorySize, GEMM_SMEM);
    cudaFuncSetAttribute(attn_mma_kernel,
                         cudaFuncAttributeMaxDynamicSharedMemorySize, ATTN_SMEM);

    // 1) Convert weights (transpose + hi/lo split)
    {
        dim3 grid(QKV_N / 32, HID / 32);
        convert_w_kernel<<<grid, 1024>>>(w_qkv, wqkvs, QKV_N);
    }
    {
        dim3 grid(HID / 32, HID / 32);
        convert_w_kernel<<<grid, 1024>>>(w_out, wouts, HID);
    }
    // 2) Convert x
    convert_act_kernel<<<(MROWS * 1024 + 255) / 256, 256>>>(x, as, MROWS);
    // 3) QKV projection (HMMA)
    {
        dim3 grid(QKV_N / BN, MROWS / BM);
        mma_gemm_kernel<<<grid, 256, GEMM_SMEM>>>(as, wqkvs, b_qkv, qkv, MROWS, QKV_N);
    }
    // 4) HMMA flash attention -> writes stacked bf16 g_as directly
    {
        dim3 grid(16, BATCH * NHEADS);
        attn_mma_kernel<<<grid, 256, ATTN_SMEM>>>(qkv, as);
    }
    // 5) Output projection (HMMA)
    {
        dim3 grid(HID / BN, MROWS / BM);
        mma_gemm_kernel<<<grid, 256, GEMM_SMEM>>>(as, wouts, b_out, out, MROWS, HID);
    }
}

// round 5
// speedup vs baseline: 2.7900x; 1.0943x over previous
#include <cuda_runtime.h>
#include <cuda_bf16.h>
#include <cstdint>
#include <math.h>

// Problem constants
#define BATCH   2
#define SEQ     2048
#define HID     1024
#define NHEADS  16
#define HD      64
#define QKV_N   3072
#define MROWS   4096
#define KS      3072          // stacked K = 3*1024

#define QSCALE  0.18033688f   // 0.125 * log2(e)

// ---------------- scratch (device globals; no allocations allowed) ----------
__device__ __nv_bfloat16 g_as[(size_t)MROWS * KS];             // stacked activations [hi,lo,hi]
__device__ __nv_bfloat16 g_wqkv_s[(size_t)QKV_N * KS];         // stacked W^T [hi,hi,lo]
__device__ __nv_bfloat16 g_wout_s[(size_t)HID * KS];
// Head-major bf16 hi/lo Q/K/V: [b*16+h][s][64]
#define HM_ELEMS ((size_t)BATCH * NHEADS * SEQ * HD)
__device__ __nv_bfloat16 g_qh[HM_ELEMS], g_ql[HM_ELEMS];
__device__ __nv_bfloat16 g_kh[HM_ELEMS], g_kl[HM_ELEMS];
__device__ __nv_bfloat16 g_vh[HM_ELEMS], g_vl[HM_ELEMS];

// ---------------- PTX helpers (base ISA only) ----------------
__device__ __forceinline__ uint32_t smem_u32(const void* p) {
    uint32_t a;
    asm("{ .reg .u64 t; cvta.to.shared.u64 t, %1; cvt.u32.u64 %0, t; }" : "=r"(a) : "l"(p));
    return a;
}

__device__ __forceinline__ void cp_async16(uint32_t s, const void* g) {
    asm volatile("cp.async.cg.shared.global [%0], [%1], 16;" :: "r"(s), "l"(g) : "memory");
}
#define CP_COMMIT() asm volatile("cp.async.commit_group;" ::: "memory")
#define CP_WAIT1()  asm volatile("cp.async.wait_group 1;"  ::: "memory")

#define LDSM_X4(R0, R1, R2, R3, ADDR)                                          \
    asm volatile("ldmatrix.sync.aligned.m8n8.x4.shared.b16 {%0,%1,%2,%3}, [%4];" \
                 : "=r"(R0), "=r"(R1), "=r"(R2), "=r"(R3) : "r"(ADDR))

#define LDSM_X4T(R0, R1, R2, R3, ADDR)                                         \
    asm volatile("ldmatrix.sync.aligned.m8n8.x4.trans.shared.b16 {%0,%1,%2,%3}, [%4];" \
                 : "=r"(R0), "=r"(R1), "=r"(R2), "=r"(R3) : "r"(ADDR))

#define MMA16816(D, A, B0, B1)                                                 \
    asm volatile("mma.sync.aligned.m16n8k16.row.col.f32.bf16.bf16.f32 "        \
                 "{%0,%1,%2,%3},{%4,%5,%6,%7},{%8,%9},{%0,%1,%2,%3};"          \
                 : "+f"((D)[0]), "+f"((D)[1]), "+f"((D)[2]), "+f"((D)[3])      \
                 : "r"((A)[0]), "r"((A)[1]), "r"((A)[2]), "r"((A)[3]),         \
                   "r"(B0), "r"(B1))

// Fast exp2 on FMA/ALU pipes (no MUFU). rel err ~1e-7.
__device__ __forceinline__ float fexp2(float x) {
    x = fmaxf(x, -125.0f);
    int   n  = __float2int_rn(x);
    float f  = x - (float)n;
    float p  = 1.535336188319500e-4f;
    p = fmaf(p, f, 1.339887440266574e-3f);
    p = fmaf(p, f, 9.618437357674640e-3f);
    p = fmaf(p, f, 5.550332471162809e-2f);
    p = fmaf(p, f, 2.402264791363012e-1f);
    p = fmaf(p, f, 6.931472028550421e-1f);
    p = fmaf(p, f, 1.0f);
    return __int_as_float(__float_as_int(p) + (n << 23));
}

__device__ __forceinline__ uint32_t packbf2(__nv_bfloat16 a, __nv_bfloat16 b) {
    __nv_bfloat162 t;
    t.x = a; t.y = b;
    return *reinterpret_cast<uint32_t*>(&t);
}

// ---------------------------------------------------------------------------
// Conversion: fp32 activations [R,1024] -> stacked bf16 [R,3072] = [hi | lo | hi]
// ---------------------------------------------------------------------------
__global__ __launch_bounds__(256) void convert_act_kernel(
    const float* __restrict__ in, __nv_bfloat16* __restrict__ out, int R)
{
    int idx = blockIdx.x * 256 + threadIdx.x;
    int total = R * 1024;
    if (idx >= total) return;
    int m = idx >> 10;
    int k = idx & 1023;
    float v = in[idx];
    __nv_bfloat16 h = __float2bfloat16(v);
    __nv_bfloat16 l = __float2bfloat16(v - __bfloat162float(h));
    size_t o = (size_t)m * KS + k;
    out[o]        = h;
    out[o + 1024] = l;
    out[o + 2048] = h;
}

// ---------------------------------------------------------------------------
// Conversion + transpose: W fp32 [K=1024, N] -> stacked bf16 [N,3072] = [hi|hi|lo]
// ---------------------------------------------------------------------------
__global__ __launch_bounds__(1024) void convert_w_kernel(
    const float* __restrict__ w, __nv_bfloat16* __restrict__ out, int N)
{
    __shared__ float tile[32][33];
    int tx = threadIdx.x & 31;
    int ty = threadIdx.x >> 5;
    int gn = blockIdx.x * 32;
    int gk = blockIdx.y * 32;
    tile[ty][tx] = w[(size_t)(gk + ty) * N + gn + tx];
    __syncthreads();
    float v = tile[tx][ty];
    __nv_bfloat16 h = __float2bfloat16(v);
    __nv_bfloat16 l = __float2bfloat16(v - __bfloat162float(h));
    size_t o = (size_t)(gn + ty) * KS + gk + tx;
    out[o]        = h;
    out[o + 1024] = h;
    out[o + 2048] = l;
}

// ---------------------------------------------------------------------------
// HMMA GEMM: 128x128x64 CTA tile, 128 threads (4 warps, 2x2), warp tile 64x64.
// mode 0: C = A@B^T + bias (fp32 out).
// mode 1: QKV epilogue — write Q(scaled)/K/V as bf16 hi/lo head-major buffers.
// ---------------------------------------------------------------------------
#define BM 128
#define BN 128
#define BK 64
#define NKITER (KS / BK)
#define TILE_A_BYTES (BM * 128)
#define TILE_B_BYTES (BN * 128)
#define STAGE_BYTES  (TILE_A_BYTES + TILE_B_BYTES)
#define GEMM_SMEM    (3 * STAGE_BYTES + 128)

__global__ __launch_bounds__(128) void mma_gemm_kernel(
    const __nv_bfloat16* __restrict__ As, const __nv_bfloat16* __restrict__ Bs,
    const float* __restrict__ bias, float* __restrict__ C, int M, int N, int mode,
    __nv_bfloat16* __restrict__ qh, __nv_bfloat16* __restrict__ ql,
    __nv_bfloat16* __restrict__ kh, __nv_bfloat16* __restrict__ kl,
    __nv_bfloat16* __restrict__ vh, __nv_bfloat16* __restrict__ vl)
{
    extern __shared__ char dsmem[];
    const uint32_t smem_base = (smem_u32(dsmem) + 127u) & ~127u;

    const int tid  = threadIdx.x;
    const int wid  = tid >> 5;
    const int lane = tid & 31;
    const int wm   = wid >> 1;     // 0..1 (64-row slab)
    const int wn   = wid & 1;      // 0..1 (64-col slab)

    const int block_row = blockIdx.y * BM;
    const int block_col = blockIdx.x * BN;

    const __nv_bfloat16* Abase = As + (size_t)block_row * KS;
    const __nv_bfloat16* Bbase = Bs + (size_t)block_col * KS;

    auto load_stage = [&](int stage, int kc) {
        const uint32_t sA = smem_base + stage * STAGE_BYTES;
        const uint32_t sB = sA + TILE_A_BYTES;
#pragma unroll
        for (int i = 0; i < 8; i++) {
            const int s   = i * 128 + tid;
            const int row = s >> 3;
            const int ch  = s & 7;
            const uint32_t sw = (uint32_t)(ch * 16) ^ (uint32_t)((row & 7) << 4);
            cp_async16(sA + row * 128 + sw, Abase + (size_t)row * KS + kc + ch * 8);
            cp_async16(sB + row * 128 + sw, Bbase + (size_t)row * KS + kc + ch * 8);
        }
        CP_COMMIT();
    };

    float acc[4][8][4];
#pragma unroll
    for (int mt = 0; mt < 4; mt++)
#pragma unroll
        for (int nt = 0; nt < 8; nt++)
#pragma unroll
            for (int r = 0; r < 4; r++) acc[mt][nt][r] = 0.0f;

    load_stage(0, 0);
    load_stage(1, BK);

    const int lrow  = lane & 15;
    const int kseg  = (lane >> 4) * 16;
    const uint32_t arow_off = (uint32_t)(wm * 64 + lrow) * 128;
    const uint32_t brow_off = (uint32_t)(wn * 64 + lrow) * 128;
    const uint32_t aswz = (uint32_t)((lrow & 7) << 4);

    for (int it = 0; it < NKITER; it++) {
        CP_WAIT1();
        __syncthreads();
        if (it + 2 < NKITER) load_stage((it + 2) % 3, (it + 2) * BK);
        else                 CP_COMMIT();

        const uint32_t sA = smem_base + (it % 3) * STAGE_BYTES;
        const uint32_t sB = sA + TILE_A_BYTES;

#pragma unroll
        for (int kt = 0; kt < 4; kt++) {
            const uint32_t koff = (uint32_t)(kt * 32 + kseg);
            uint32_t a[4][4], bb[4][4];
#pragma unroll
            for (int mt = 0; mt < 4; mt++) {
                const uint32_t addr = sA + arow_off + (uint32_t)(mt * 16 * 128)
                                    + (koff ^ aswz);
                LDSM_X4(a[mt][0], a[mt][1], a[mt][2], a[mt][3], addr);
            }
#pragma unroll
            for (int pr = 0; pr < 4; pr++) {
                const uint32_t addr = sB + brow_off + (uint32_t)(pr * 16 * 128)
                                    + (koff ^ aswz);
                LDSM_X4(bb[pr][0], bb[pr][1], bb[pr][2], bb[pr][3], addr);
            }
#pragma unroll
            for (int mt = 0; mt < 4; mt++)
#pragma unroll
                for (int nt = 0; nt < 8; nt++) {
                    const int pr = nt >> 1, sub = nt & 1;
                    MMA16816(acc[mt][nt], a[mt], bb[pr][sub], bb[pr][sub + 2]);
                }
        }
        __syncthreads();
    }

    const int rbase = block_row + wm * 64 + (lane >> 2);
    const int cbase = block_col + wn * 64 + (lane & 3) * 2;

    if (mode == 0) {
#pragma unroll
        for (int mt = 0; mt < 4; mt++) {
#pragma unroll
            for (int nt = 0; nt < 8; nt++) {
                const int col = cbase + nt * 8;
                const float bx = bias[col];
                const float by = bias[col + 1];
                const int r0 = rbase + mt * 16;
                float2 o0 = { acc[mt][nt][0] + bx, acc[mt][nt][1] + by };
                float2 o1 = { acc[mt][nt][2] + bx, acc[mt][nt][3] + by };
                *(float2*)(C + (size_t)r0 * N + col)       = o0;
                *(float2*)(C + (size_t)(r0 + 8) * N + col) = o1;
            }
        }
    } else {
        // QKV epilogue: split into Q/K/V head-major bf16 hi/lo.
#pragma unroll
        for (int mt = 0; mt < 4; mt++) {
#pragma unroll
            for (int nt = 0; nt < 8; nt++) {
                const int col  = cbase + nt * 8;     // even
                const int part = col >> 10;          // warp-uniform
                const int hh   = (col >> 6) & 15;
                const int dd   = col & 63;
                const float bx = bias[col];
                const float by = bias[col + 1];
                __nv_bfloat16* dh = part == 0 ? qh : (part == 1 ? kh : vh);
                __nv_bfloat16* dl = part == 0 ? ql : (part == 1 ? kl : vl);
                const float sc = part == 0 ? QSCALE : 1.0f;
#pragma unroll
                for (int rr = 0; rr < 2; rr++) {
                    const int r = rbase + mt * 16 + rr * 8;
                    const float v0 = (acc[mt][nt][rr * 2 + 0] + bx) * sc;
                    const float v1 = (acc[mt][nt][rr * 2 + 1] + by) * sc;
                    const __nv_bfloat16 h0 = __float2bfloat16(v0);
                    const __nv_bfloat16 h1 = __float2bfloat16(v1);
                    const size_t off =
                        (((size_t)((r >> 11) * 16 + hh)) * SEQ + (r & 2047)) * 64 + dd;
                    *(uint32_t*)(dh + off) = packbf2(h0, h1);
                    *(uint32_t*)(dl + off) =
                        packbf2(__float2bfloat16(v0 - __bfloat162float(h0)),
                                __float2bfloat16(v1 - __bfloat162float(h1)));
                }
            }
        }
    }
}

// ---------------------------------------------------------------------------
// HMMA causal flash attention, fully bf16-fed, 3-stage cp.async pipeline.
// One CTA = 128 queries of one (b,h); 8 warps x 16 rows; 64-key tiles.
// smem: QH 16K | QL 16K | 3 stages x {KH,KL,VH,VL 8K each} = 128KB
// ---------------------------------------------------------------------------
#define KV_STAGE_BYTES 32768
#define ATTN_SMEM (32768 + 3 * KV_STAGE_BYTES + 128)

__global__ __launch_bounds__(256) void attn_mma_kernel(
    const __nv_bfloat16* __restrict__ qh_g, const __nv_bfloat16* __restrict__ ql_g,
    const __nv_bfloat16* __restrict__ kh_g, const __nv_bfloat16* __restrict__ kl_g,
    const __nv_bfloat16* __restrict__ vh_g, const __nv_bfloat16* __restrict__ vl_g,
    __nv_bfloat16* __restrict__ outs)
{
    extern __shared__ char sm[];
    const uint32_t base = (smem_u32(sm) + 127u) & ~127u;
    const uint32_t sQH = base;
    const uint32_t sQL = base + 16384;
    const uint32_t kvbase = base + 32768;

    const int tid  = threadIdx.x;
    const int lane = tid & 31;
    const int wid  = tid >> 5;
    const int qb   = 15 - (int)blockIdx.x;     // heavy blocks first
    const int bh   = blockIdx.y;
    const int b    = bh >> 4;
    const int h    = bh & 15;
    const size_t hrow = (size_t)bh * SEQ;      // row base within head-major buffers

    // ---- Q tile cp.async (part of group 0) ----
#pragma unroll
    for (int i = 0; i < 4; i++) {
        const int s   = i * 256 + tid;
        const int row = s >> 3;
        const int ch  = s & 7;
        const uint32_t sw = (uint32_t)(ch * 16) ^ (uint32_t)((row & 7) << 4);
        const size_t gofs = (hrow + qb * 128 + row) * 64 + ch * 8;
        cp_async16(sQH + row * 128 + sw, qh_g + gofs);
        cp_async16(sQL + row * 128 + sw, ql_g + gofs);
    }

    auto load_kv = [&](int stage, int k0) {
        const uint32_t sb = kvbase + stage * KV_STAGE_BYTES;
#pragma unroll
        for (int i = 0; i < 2; i++) {
            const int s   = i * 256 + tid;
            const int row = s >> 3;
            const int ch  = s & 7;
            const uint32_t sw = (uint32_t)(ch * 16) ^ (uint32_t)((row & 7) << 4);
            const uint32_t so = row * 128 + sw;
            const size_t gofs = (hrow + k0 + row) * 64 + ch * 8;
            cp_async16(sb + so,         kh_g + gofs);
            cp_async16(sb + 8192 + so,  kl_g + gofs);
            cp_async16(sb + 16384 + so, vh_g + gofs);
            cp_async16(sb + 24576 + so, vl_g + gofs);
        }
        CP_COMMIT();
    };

    const int nk = (qb + 1) * 2;
    load_kv(0, 0);        // group 0 (with Q)
    load_kv(1, 64);       // group 1

    float acc_o[8][4];
#pragma unroll
    for (int nt = 0; nt < 8; nt++)
#pragma unroll
        for (int r = 0; r < 4; r++) acc_o[nt][r] = 0.0f;
    float m0 = -1e30f, m1 = -1e30f, l0 = 0.0f, l1 = 0.0f;

    const int r0      = lane >> 2;
    const int qrow_w  = qb * 128 + wid * 16;
    const int qg0     = qrow_w + r0;

    const int a_r = wid * 16 + (lane & 15);
    const int a_c = (lane >> 4) * 16;
    const uint32_t a_row_off = (uint32_t)(a_r * 128);
    const uint32_t a_sw = (uint32_t)((a_r & 7) << 4);
    const int g      = lane >> 3;
    const int br_off = lane & 7;

    for (int t = 0; t < nk; t++) {
        const int k0 = t * 64;
        CP_WAIT1();
        __syncthreads();
        if (t + 2 < nk) load_kv((t + 2) % 3, (t + 2) * 64);
        else            CP_COMMIT();

        const uint32_t st  = kvbase + (t % 3) * KV_STAGE_BYTES;
        const uint32_t sKH = st;
        const uint32_t sKL = st + 8192;
        const uint32_t sVH = st + 16384;
        const uint32_t sVL = st + 24576;

        // ---- S = Q K^T (3-pass hi/lo) ----
        float s[8][4];
#pragma unroll
        for (int nt = 0; nt < 8; nt++)
#pragma unroll
            for (int r = 0; r < 4; r++) s[nt][r] = 0.0f;

#pragma unroll
        for (int kc = 0; kc < 4; kc++) {
            uint32_t qhf[4], qlf[4];
            const uint32_t qoff = ((uint32_t)(kc * 32 + a_c)) ^ a_sw;
            LDSM_X4(qhf[0], qhf[1], qhf[2], qhf[3], sQH + a_row_off + qoff);
            LDSM_X4(qlf[0], qlf[1], qlf[2], qlf[3], sQL + a_row_off + qoff);
#pragma unroll
            for (int np = 0; np < 4; np++) {
                const int brow = np * 16 + ((g & 2) << 2) + br_off;
                const uint32_t boff = ((uint32_t)(kc * 32 + ((g & 1) << 4)))
                                    ^ (uint32_t)((brow & 7) << 4);
                const uint32_t rb = (uint32_t)(brow * 128) + boff;
                uint32_t b0, b1, b2, b3;
                LDSM_X4(b0, b1, b2, b3, sKH + rb);
                MMA16816(s[2 * np],     qhf, b0, b1);
                MMA16816(s[2 * np + 1], qhf, b2, b3);
                MMA16816(s[2 * np],     qlf, b0, b1);
                MMA16816(s[2 * np + 1], qlf, b2, b3);
                LDSM_X4(b0, b1, b2, b3, sKL + rb);
                MMA16816(s[2 * np],     qhf, b0, b1);
                MMA16816(s[2 * np + 1], qhf, b2, b3);
            }
        }

        // ---- causal mask ----
        if (k0 + 63 > qrow_w) {
#pragma unroll
            for (int nt = 0; nt < 8; nt++) {
                const int kg0 = k0 + nt * 8 + 2 * (lane & 3);
                if (kg0     > qg0)     s[nt][0] = -1e30f;
                if (kg0 + 1 > qg0)     s[nt][1] = -1e30f;
                if (kg0     > qg0 + 8) s[nt][2] = -1e30f;
                if (kg0 + 1 > qg0 + 8) s[nt][3] = -1e30f;
            }
        }

        // ---- online softmax (base-2) ----
        float rx0 = -1e30f, rx1 = -1e30f;
#pragma unroll
        for (int nt = 0; nt < 8; nt++) {
            rx0 = fmaxf(rx0, fmaxf(s[nt][0], s[nt][1]));
            rx1 = fmaxf(rx1, fmaxf(s[nt][2], s[nt][3]));
        }
        rx0 = fmaxf(rx0, __shfl_xor_sync(0xffffffffu, rx0, 1));
        rx0 = fmaxf(rx0, __shfl_xor_sync(0xffffffffu, rx0, 2));
        rx1 = fmaxf(rx1, __shfl_xor_sync(0xffffffffu, rx1, 1));
        rx1 = fmaxf(rx1, __shfl_xor_sync(0xffffffffu, rx1, 2));
        const float mn0 = fmaxf(m0, rx0);
        const float mn1 = fmaxf(m1, rx1);
        const float sc0 = fexp2(m0 - mn0);
        const float sc1 = fexp2(m1 - mn1);
        m0 = mn0; m1 = mn1;
        l0 *= sc0; l1 *= sc1;
#pragma unroll
        for (int nt = 0; nt < 8; nt++) {
            acc_o[nt][0] *= sc0; acc_o[nt][1] *= sc0;
            acc_o[nt][2] *= sc1; acc_o[nt][3] *= sc1;
        }

        uint32_t ph[4][4], pl[4][4];
#pragma unroll
        for (int nt = 0; nt < 8; nt++) {
            const float p0 = fexp2(s[nt][0] - m0);
            const float p1 = fexp2(s[nt][1] - m0);
            const float p2 = fexp2(s[nt][2] - m1);
            const float p3 = fexp2(s[nt][3] - m1);
            l0 += p0 + p1;
            l1 += p2 + p3;
            const __nv_bfloat16 h0 = __float2bfloat16(p0);
            const __nv_bfloat16 h1 = __float2bfloat16(p1);
            const __nv_bfloat16 h2 = __float2bfloat16(p2);
            const __nv_bfloat16 h3 = __float2bfloat16(p3);
            const int kc = nt >> 1;
            const int rr = (nt & 1) * 2;
            ph[kc][rr]     = packbf2(h0, h1);
            ph[kc][rr + 1] = packbf2(h2, h3);
            pl[kc][rr]     = packbf2(__float2bfloat16(p0 - __bfloat162float(h0)),
                                     __float2bfloat16(p1 - __bfloat162float(h1)));
            pl[kc][rr + 1] = packbf2(__float2bfloat16(p2 - __bfloat162float(h2)),
                                     __float2bfloat16(p3 - __bfloat162float(h3)));
        }

        // ---- O += P V (3-pass hi/lo, ldmatrix.trans for V) ----
#pragma unroll
        for (int kc = 0; kc < 4; kc++) {
#pragma unroll
            for (int np = 0; np < 4; np++) {
                const int vrow = kc * 16 + ((g & 1) << 3) + br_off;
                const uint32_t voff = ((uint32_t)(np * 32 + ((g & 2) << 3)))
                                    ^ (uint32_t)((vrow & 7) << 4);
                const uint32_t rv = (uint32_t)(vrow * 128) + voff;
                uint32_t b0, b1, b2, b3;
                LDSM_X4T(b0, b1, b2, b3, sVH + rv);
                MMA16816(acc_o[2 * np],     ph[kc], b0, b1);
                MMA16816(acc_o[2 * np + 1], ph[kc], b2, b3);
                MMA16816(acc_o[2 * np],     pl[kc], b0, b1);
                MMA16816(acc_o[2 * np + 1], pl[kc], b2, b3);
                LDSM_X4T(b0, b1, b2, b3, sVL + rv);
                MMA16816(acc_o[2 * np],     ph[kc], b0, b1);
                MMA16816(acc_o[2 * np + 1], ph[kc], b2, b3);
            }
        }
        __syncthreads();
    }

    // ---- epilogue: normalize, write stacked bf16 hi/lo rows of g_as ----
    l0 += __shfl_xor_sync(0xffffffffu, l0, 1);
    l0 += __shfl_xor_sync(0xffffffffu, l0, 2);
    l1 += __shfl_xor_sync(0xffffffffu, l1, 1);
    l1 += __shfl_xor_sync(0xffffffffu, l1, 2);
    const float inv0 = 1.0f / l0;
    const float inv1 = 1.0f / l1;

    const size_t row0 = (size_t)(b * SEQ + qg0) * KS;
    const size_t row1 = row0 + 8 * KS;
    const int colbase = h * HD + 2 * (lane & 3);
#pragma unroll
    for (int nt = 0; nt < 8; nt++) {
        const int col = colbase + nt * 8;
        const float v0 = acc_o[nt][0] * inv0;
        const float v1 = acc_o[nt][1] * inv0;
        const float v2 = acc_o[nt][2] * inv1;
        const float v3 = acc_o[nt][3] * inv1;
        const __nv_bfloat16 h0 = __float2bfloat16(v0);
        const __nv_bfloat16 h1 = __float2bfloat16(v1);
        const __nv_bfloat16 h2 = __float2bfloat16(v2);
        const __nv_bfloat16 h3 = __float2bfloat16(v3);
        const uint32_t hi01 = packbf2(h0, h1);
        const uint32_t lo01 = packbf2(__float2bfloat16(v0 - __bfloat162float(h0)),
                                      __float2bfloat16(v1 - __bfloat162float(h1)));
        const uint32_t hi23 = packbf2(h2, h3);
        const uint32_t lo23 = packbf2(__float2bfloat16(v2 - __bfloat162float(h2)),
                                      __float2bfloat16(v3 - __bfloat162float(h3)));
        *(uint32_t*)(outs + row0 + col)        = hi01;
        *(uint32_t*)(outs + row0 + col + 1024) = lo01;
        *(uint32_t*)(outs + row0 + col + 2048) = hi01;
        *(uint32_t*)(outs + row1 + col)        = hi23;
        *(uint32_t*)(outs + row1 + col + 1024) = lo23;
        *(uint32_t*)(outs + row1 + col + 2048) = hi23;
    }
}

// ---------------------------------------------------------------------------
extern "C" void kernel_launch(void* const* d_in, const int* in_sizes, int n_in,
                              void* d_out, int out_size)
{
    const float* x     = (const float*)d_in[0];
    const float* w_qkv = (const float*)d_in[1];
    const float* b_qkv = (const float*)d_in[2];
    const float* w_out = (const float*)d_in[3];
    const float* b_out = (const float*)d_in[4];
    float* out = (float*)d_out;

    __nv_bfloat16 *as, *wqkvs, *wouts, *qh, *ql, *kh, *kl, *vh, *vl;
    cudaGetSymbolAddress((void**)&as,    g_as);
    cudaGetSymbolAddress((void**)&wqkvs, g_wqkv_s);
    cudaGetSymbolAddress((void**)&wouts, g_wout_s);
    cudaGetSymbolAddress((void**)&qh, g_qh);
    cudaGetSymbolAddress((void**)&ql, g_ql);
    cudaGetSymbolAddress((void**)&kh, g_kh);
    cudaGetSymbolAddress((void**)&kl, g_kl);
    cudaGetSymbolAddress((void**)&vh, g_vh);
    cudaGetSymbolAddress((void**)&vl, g_vl);

    cudaFuncSetAttribute(mma_gemm_kernel,
                         cudaFuncAttributeMaxDynamicSharedMemorySize, GEMM_SMEM);
    cudaFuncSetAttribute(attn_mma_kernel,
                         cudaFuncAttributeMaxDynamicSharedMemorySize, ATTN_SMEM);

    // 1) Convert weights (transpose + hi/lo split)
    {
        dim3 grid(QKV_N / 32, HID / 32);
        convert_w_kernel<<<grid, 1024>>>(w_qkv, wqkvs, QKV_N);
    }
    {
        dim3 grid(HID / 32, HID / 32);
        convert_w_kernel<<<grid, 1024>>>(w_out, wouts, HID);
    }
    // 2) Convert x
    convert_act_kernel<<<(MROWS * 1024 + 255) / 256, 256>>>(x, as, MROWS);
    // 3) QKV projection -> head-major bf16 hi/lo Q/K/V (mode 1)
    {
        dim3 grid(QKV_N / BN, MROWS / BM);
        mma_gemm_kernel<<<grid, 128, GEMM_SMEM>>>(as, wqkvs, b_qkv, nullptr,
                                                  MROWS, QKV_N, 1,
                                                  qh, ql, kh, kl, vh, vl);
    }
    // 4) HMMA flash attention (pipelined bf16 feed) -> stacked g_as
    {
        dim3 grid(16, BATCH * NHEADS);
        attn_mma_kernel<<<grid, 256, ATTN_SMEM>>>(qh, ql, kh, kl, vh, vl, as);
    }
    // 5) Output projection (mode 0)
    {
        dim3 grid(HID / BN, MROWS / BM);
        mma_gemm_kernel<<<grid, 128, GEMM_SMEM>>>(as, wouts, b_out, out,
                                                  MROWS, HID, 0,
                                                  nullptr, nullptr, nullptr,
                                                  nullptr, nullptr, nullptr);
    }
}

// round 6
// speedup vs baseline: 2.8154x; 1.0091x over previous
#include <cuda_runtime.h>
#include <cuda_bf16.h>
#include <cstdint>
#include <math.h>

// Problem constants
#define BATCH   2
#define SEQ     2048
#define HID     1024
#define NHEADS  16
#define HD      64
#define QKV_N   3072
#define MROWS   4096
#define KS      3072          // stacked K = 3*1024

#define QSCALE  0.18033688f   // 0.125 * log2(e)

// ---------------- scratch (device globals; no allocations allowed) ----------
__device__ __nv_bfloat16 g_as[(size_t)MROWS * KS];             // stacked activations [hi,lo,hi]
__device__ __nv_bfloat16 g_wqkv_s[(size_t)QKV_N * KS];         // stacked W^T [hi,hi,lo]
__device__ __nv_bfloat16 g_wout_s[(size_t)HID * KS];
// Head-major bf16 hi/lo Q/K/V: [b*16+h][s][64]
#define HM_ELEMS ((size_t)BATCH * NHEADS * SEQ * HD)
__device__ __nv_bfloat16 g_qh[HM_ELEMS], g_ql[HM_ELEMS];
__device__ __nv_bfloat16 g_kh[HM_ELEMS], g_kl[HM_ELEMS];
__device__ __nv_bfloat16 g_vh[HM_ELEMS], g_vl[HM_ELEMS];

// ---------------- PTX helpers (base ISA only) ----------------
__device__ __forceinline__ uint32_t smem_u32(const void* p) {
    uint32_t a;
    asm("{ .reg .u64 t; cvta.to.shared.u64 t, %1; cvt.u32.u64 %0, t; }" : "=r"(a) : "l"(p));
    return a;
}

__device__ __forceinline__ void cp_async16(uint32_t s, const void* g) {
    asm volatile("cp.async.cg.shared.global [%0], [%1], 16;" :: "r"(s), "l"(g) : "memory");
}
#define CP_COMMIT() asm volatile("cp.async.commit_group;" ::: "memory")
#define CP_WAIT1()  asm volatile("cp.async.wait_group 1;"  ::: "memory")

#define LDSM_X4(R0, R1, R2, R3, ADDR)                                          \
    asm volatile("ldmatrix.sync.aligned.m8n8.x4.shared.b16 {%0,%1,%2,%3}, [%4];" \
                 : "=r"(R0), "=r"(R1), "=r"(R2), "=r"(R3) : "r"(ADDR))

#define LDSM_X4T(R0, R1, R2, R3, ADDR)                                         \
    asm volatile("ldmatrix.sync.aligned.m8n8.x4.trans.shared.b16 {%0,%1,%2,%3}, [%4];" \
                 : "=r"(R0), "=r"(R1), "=r"(R2), "=r"(R3) : "r"(ADDR))

#define MMA16816(D, A, B0, B1)                                                 \
    asm volatile("mma.sync.aligned.m16n8k16.row.col.f32.bf16.bf16.f32 "        \
                 "{%0,%1,%2,%3},{%4,%5,%6,%7},{%8,%9},{%0,%1,%2,%3};"          \
                 : "+f"((D)[0]), "+f"((D)[1]), "+f"((D)[2]), "+f"((D)[3])      \
                 : "r"((A)[0]), "r"((A)[1]), "r"((A)[2]), "r"((A)[3]),         \
                   "r"(B0), "r"(B1))

// Fast exp2 on FMA/ALU pipes (no MUFU). rel err ~1e-7.
__device__ __forceinline__ float fexp2(float x) {
    x = fmaxf(x, -125.0f);
    int   n  = __float2int_rn(x);
    float f  = x - (float)n;
    float p  = 1.535336188319500e-4f;
    p = fmaf(p, f, 1.339887440266574e-3f);
    p = fmaf(p, f, 9.618437357674640e-3f);
    p = fmaf(p, f, 5.550332471162809e-2f);
    p = fmaf(p, f, 2.402264791363012e-1f);
    p = fmaf(p, f, 6.931472028550421e-1f);
    p = fmaf(p, f, 1.0f);
    return __int_as_float(__float_as_int(p) + (n << 23));
}

__device__ __forceinline__ uint32_t packbf2(__nv_bfloat16 a, __nv_bfloat16 b) {
    __nv_bfloat162 t;
    t.x = a; t.y = b;
    return *reinterpret_cast<uint32_t*>(&t);
}

// ---------------------------------------------------------------------------
// Conversion: fp32 activations [R,1024] -> stacked bf16 [R,3072] = [hi | lo | hi]
// ---------------------------------------------------------------------------
__global__ __launch_bounds__(256) void convert_act_kernel(
    const float* __restrict__ in, __nv_bfloat16* __restrict__ out, int R)
{
    int idx = blockIdx.x * 256 + threadIdx.x;
    int total = R * 1024;
    if (idx >= total) return;
    int m = idx >> 10;
    int k = idx & 1023;
    float v = in[idx];
    __nv_bfloat16 h = __float2bfloat16(v);
    __nv_bfloat16 l = __float2bfloat16(v - __bfloat162float(h));
    size_t o = (size_t)m * KS + k;
    out[o]        = h;
    out[o + 1024] = l;
    out[o + 2048] = h;
}

// ---------------------------------------------------------------------------
// Conversion + transpose: W fp32 [K=1024, N] -> stacked bf16 [N,3072] = [hi|hi|lo]
// ---------------------------------------------------------------------------
__global__ __launch_bounds__(1024) void convert_w_kernel(
    const float* __restrict__ w, __nv_bfloat16* __restrict__ out, int N)
{
    __shared__ float tile[32][33];
    int tx = threadIdx.x & 31;
    int ty = threadIdx.x >> 5;
    int gn = blockIdx.x * 32;
    int gk = blockIdx.y * 32;
    tile[ty][tx] = w[(size_t)(gk + ty) * N + gn + tx];
    __syncthreads();
    float v = tile[tx][ty];
    __nv_bfloat16 h = __float2bfloat16(v);
    __nv_bfloat16 l = __float2bfloat16(v - __bfloat162float(h));
    size_t o = (size_t)(gn + ty) * KS + gk + tx;
    out[o]        = h;
    out[o + 1024] = h;
    out[o + 2048] = l;
}

// ---------------------------------------------------------------------------
// HMMA GEMM: 128x128x64 CTA tile, 256 threads (8 warps, 2x4), warp tile 64x32.
// kt-level fragment double-buffering: ldsm for kt+1 issued before MMAs of kt.
// mode 0: C = A@B^T + bias (fp32 out).
// mode 1: QKV epilogue — write Q(scaled)/K/V as bf16 hi/lo head-major buffers.
// ---------------------------------------------------------------------------
#define BM 128
#define BN 128
#define BK 64
#define NKITER (KS / BK)
#define TILE_A_BYTES (BM * 128)
#define TILE_B_BYTES (BN * 128)
#define STAGE_BYTES  (TILE_A_BYTES + TILE_B_BYTES)
#define GEMM_SMEM    (3 * STAGE_BYTES + 128)

__global__ __launch_bounds__(256, 2) void mma_gemm_kernel(
    const __nv_bfloat16* __restrict__ As, const __nv_bfloat16* __restrict__ Bs,
    const float* __restrict__ bias, float* __restrict__ C, int M, int N, int mode,
    __nv_bfloat16* __restrict__ qh, __nv_bfloat16* __restrict__ ql,
    __nv_bfloat16* __restrict__ kh, __nv_bfloat16* __restrict__ kl,
    __nv_bfloat16* __restrict__ vh, __nv_bfloat16* __restrict__ vl)
{
    extern __shared__ char dsmem[];
    const uint32_t smem_base = (smem_u32(dsmem) + 127u) & ~127u;

    const int tid  = threadIdx.x;
    const int wid  = tid >> 5;
    const int lane = tid & 31;
    const int wm   = wid >> 2;     // 0..1 (64-row slab)
    const int wn   = wid & 3;      // 0..3 (32-col slab)

    const int block_row = blockIdx.y * BM;
    const int block_col = blockIdx.x * BN;

    const __nv_bfloat16* Abase = As + (size_t)block_row * KS;
    const __nv_bfloat16* Bbase = Bs + (size_t)block_col * KS;

    auto load_stage = [&](int stage, int kc) {
        const uint32_t sA = smem_base + stage * STAGE_BYTES;
        const uint32_t sB = sA + TILE_A_BYTES;
#pragma unroll
        for (int i = 0; i < 4; i++) {
            const int s   = i * 256 + tid;
            const int row = s >> 3;
            const int ch  = s & 7;
            const uint32_t sw = (uint32_t)(ch * 16) ^ (uint32_t)((row & 7) << 4);
            cp_async16(sA + row * 128 + sw, Abase + (size_t)row * KS + kc + ch * 8);
            cp_async16(sB + row * 128 + sw, Bbase + (size_t)row * KS + kc + ch * 8);
        }
        CP_COMMIT();
    };

    float acc[4][4][4];
#pragma unroll
    for (int mt = 0; mt < 4; mt++)
#pragma unroll
        for (int nt = 0; nt < 4; nt++)
#pragma unroll
            for (int r = 0; r < 4; r++) acc[mt][nt][r] = 0.0f;

    load_stage(0, 0);
    load_stage(1, BK);

    const int lrow  = lane & 15;
    const int kseg  = (lane >> 4) * 16;
    const uint32_t arow_off = (uint32_t)(wm * 64 + lrow) * 128;
    const uint32_t brow_off = (uint32_t)(wn * 32 + lrow) * 128;
    const uint32_t aswz = (uint32_t)((lrow & 7) << 4);

    uint32_t afrag[2][4][4], bfrag[2][2][4];

    for (int it = 0; it < NKITER; it++) {
        CP_WAIT1();
        __syncthreads();
        if (it + 2 < NKITER) load_stage((it + 2) % 3, (it + 2) * BK);
        else                 CP_COMMIT();

        const uint32_t sA = smem_base + (it % 3) * STAGE_BYTES;
        const uint32_t sB = sA + TILE_A_BYTES;

        // preload fragments for kt = 0
        {
            const uint32_t koff = (uint32_t)kseg ^ aswz;
#pragma unroll
            for (int mt = 0; mt < 4; mt++)
                LDSM_X4(afrag[0][mt][0], afrag[0][mt][1],
                        afrag[0][mt][2], afrag[0][mt][3],
                        sA + arow_off + (uint32_t)(mt * 2048) + koff);
#pragma unroll
            for (int pr = 0; pr < 2; pr++)
                LDSM_X4(bfrag[0][pr][0], bfrag[0][pr][1],
                        bfrag[0][pr][2], bfrag[0][pr][3],
                        sB + brow_off + (uint32_t)(pr * 2048) + koff);
        }

#pragma unroll
        for (int kt = 0; kt < 4; kt++) {
            const int cur = kt & 1;
            if (kt < 3) {
                const int nxt = cur ^ 1;
                const uint32_t koff = ((uint32_t)((kt + 1) * 32 + kseg)) ^ aswz;
#pragma unroll
                for (int mt = 0; mt < 4; mt++)
                    LDSM_X4(afrag[nxt][mt][0], afrag[nxt][mt][1],
                            afrag[nxt][mt][2], afrag[nxt][mt][3],
                            sA + arow_off + (uint32_t)(mt * 2048) + koff);
#pragma unroll
                for (int pr = 0; pr < 2; pr++)
                    LDSM_X4(bfrag[nxt][pr][0], bfrag[nxt][pr][1],
                            bfrag[nxt][pr][2], bfrag[nxt][pr][3],
                            sB + brow_off + (uint32_t)(pr * 2048) + koff);
            }
#pragma unroll
            for (int mt = 0; mt < 4; mt++)
#pragma unroll
                for (int nt = 0; nt < 4; nt++) {
                    const int pr = nt >> 1, sub = nt & 1;
                    MMA16816(acc[mt][nt], afrag[cur][mt],
                             bfrag[cur][pr][sub], bfrag[cur][pr][sub + 2]);
                }
        }
        __syncthreads();
    }

    const int rbase = block_row + wm * 64 + (lane >> 2);
    const int cbase = block_col + wn * 32 + (lane & 3) * 2;

    if (mode == 0) {
#pragma unroll
        for (int mt = 0; mt < 4; mt++) {
#pragma unroll
            for (int nt = 0; nt < 4; nt++) {
                const int col = cbase + nt * 8;
                const float bx = bias[col];
                const float by = bias[col + 1];
                const int r0 = rbase + mt * 16;
                float2 o0 = { acc[mt][nt][0] + bx, acc[mt][nt][1] + by };
                float2 o1 = { acc[mt][nt][2] + bx, acc[mt][nt][3] + by };
                *(float2*)(C + (size_t)r0 * N + col)       = o0;
                *(float2*)(C + (size_t)(r0 + 8) * N + col) = o1;
            }
        }
    } else {
        // QKV epilogue: split into Q/K/V head-major bf16 hi/lo.
#pragma unroll
        for (int mt = 0; mt < 4; mt++) {
#pragma unroll
            for (int nt = 0; nt < 4; nt++) {
                const int col  = cbase + nt * 8;     // even
                const int part = col >> 10;          // warp-uniform
                const int hh   = (col >> 6) & 15;
                const int dd   = col & 63;
                const float bx = bias[col];
                const float by = bias[col + 1];
                __nv_bfloat16* dh = part == 0 ? qh : (part == 1 ? kh : vh);
                __nv_bfloat16* dl = part == 0 ? ql : (part == 1 ? kl : vl);
                const float sc = part == 0 ? QSCALE : 1.0f;
#pragma unroll
                for (int rr = 0; rr < 2; rr++) {
                    const int r = rbase + mt * 16 + rr * 8;
                    const float v0 = (acc[mt][nt][rr * 2 + 0] + bx) * sc;
                    const float v1 = (acc[mt][nt][rr * 2 + 1] + by) * sc;
                    const __nv_bfloat16 h0 = __float2bfloat16(v0);
                    const __nv_bfloat16 h1 = __float2bfloat16(v1);
                    const size_t off =
                        (((size_t)((r >> 11) * 16 + hh)) * SEQ + (r & 2047)) * 64 + dd;
                    *(uint32_t*)(dh + off) = packbf2(h0, h1);
                    *(uint32_t*)(dl + off) =
                        packbf2(__float2bfloat16(v0 - __bfloat162float(h0)),
                                __float2bfloat16(v1 - __bfloat162float(h1)));
                }
            }
        }
    }
}

// ---------------------------------------------------------------------------
// HMMA causal flash attention, fully bf16-fed, 3-stage cp.async pipeline.
// One CTA = 128 queries of one (b,h); 8 warps x 16 rows; 64-key tiles.
// smem: QH 16K | QL 16K | 3 stages x {KH,KL,VH,VL 8K each} = 128KB
// ---------------------------------------------------------------------------
#define KV_STAGE_BYTES 32768
#define ATTN_SMEM (32768 + 3 * KV_STAGE_BYTES + 128)

__global__ __launch_bounds__(256) void attn_mma_kernel(
    const __nv_bfloat16* __restrict__ qh_g, const __nv_bfloat16* __restrict__ ql_g,
    const __nv_bfloat16* __restrict__ kh_g, const __nv_bfloat16* __restrict__ kl_g,
    const __nv_bfloat16* __restrict__ vh_g, const __nv_bfloat16* __restrict__ vl_g,
    __nv_bfloat16* __restrict__ outs)
{
    extern __shared__ char sm[];
    const uint32_t base = (smem_u32(sm) + 127u) & ~127u;
    const uint32_t sQH = base;
    const uint32_t sQL = base + 16384;
    const uint32_t kvbase = base + 32768;

    const int tid  = threadIdx.x;
    const int lane = tid & 31;
    const int wid  = tid >> 5;
    const int qb   = 15 - (int)blockIdx.x;     // heavy blocks first
    const int bh   = blockIdx.y;
    const int b    = bh >> 4;
    const int h    = bh & 15;
    const size_t hrow = (size_t)bh * SEQ;

    // ---- Q tile cp.async (part of group 0) ----
#pragma unroll
    for (int i = 0; i < 4; i++) {
        const int s   = i * 256 + tid;
        const int row = s >> 3;
        const int ch  = s & 7;
        const uint32_t sw = (uint32_t)(ch * 16) ^ (uint32_t)((row & 7) << 4);
        const size_t gofs = (hrow + qb * 128 + row) * 64 + ch * 8;
        cp_async16(sQH + row * 128 + sw, qh_g + gofs);
        cp_async16(sQL + row * 128 + sw, ql_g + gofs);
    }

    auto load_kv = [&](int stage, int k0) {
        const uint32_t sb = kvbase + stage * KV_STAGE_BYTES;
#pragma unroll
        for (int i = 0; i < 2; i++) {
            const int s   = i * 256 + tid;
            const int row = s >> 3;
            const int ch  = s & 7;
            const uint32_t sw = (uint32_t)(ch * 16) ^ (uint32_t)((row & 7) << 4);
            const uint32_t so = row * 128 + sw;
            const size_t gofs = (hrow + k0 + row) * 64 + ch * 8;
            cp_async16(sb + so,         kh_g + gofs);
            cp_async16(sb + 8192 + so,  kl_g + gofs);
            cp_async16(sb + 16384 + so, vh_g + gofs);
            cp_async16(sb + 24576 + so, vl_g + gofs);
        }
        CP_COMMIT();
    };

    const int nk = (qb + 1) * 2;
    load_kv(0, 0);
    load_kv(1, 64);

    float acc_o[8][4];
#pragma unroll
    for (int nt = 0; nt < 8; nt++)
#pragma unroll
        for (int r = 0; r < 4; r++) acc_o[nt][r] = 0.0f;
    float m0 = -1e30f, m1 = -1e30f, l0 = 0.0f, l1 = 0.0f;

    const int r0      = lane >> 2;
    const int qrow_w  = qb * 128 + wid * 16;
    const int qg0     = qrow_w + r0;

    const int a_r = wid * 16 + (lane & 15);
    const int a_c = (lane >> 4) * 16;
    const uint32_t a_row_off = (uint32_t)(a_r * 128);
    const uint32_t a_sw = (uint32_t)((a_r & 7) << 4);
    const int g      = lane >> 3;
    const int br_off = lane & 7;

    for (int t = 0; t < nk; t++) {
        const int k0 = t * 64;
        CP_WAIT1();
        __syncthreads();
        if (t + 2 < nk) load_kv((t + 2) % 3, (t + 2) * 64);
        else            CP_COMMIT();

        const uint32_t st  = kvbase + (t % 3) * KV_STAGE_BYTES;
        const uint32_t sKH = st;
        const uint32_t sKL = st + 8192;
        const uint32_t sVH = st + 16384;
        const uint32_t sVL = st + 24576;

        // ---- S = Q K^T (3-pass hi/lo) ----
        float s[8][4];
#pragma unroll
        for (int nt = 0; nt < 8; nt++)
#pragma unroll
            for (int r = 0; r < 4; r++) s[nt][r] = 0.0f;

#pragma unroll
        for (int kc = 0; kc < 4; kc++) {
            uint32_t qhf[4], qlf[4];
            const uint32_t qoff = ((uint32_t)(kc * 32 + a_c)) ^ a_sw;
            LDSM_X4(qhf[0], qhf[1], qhf[2], qhf[3], sQH + a_row_off + qoff);
            LDSM_X4(qlf[0], qlf[1], qlf[2], qlf[3], sQL + a_row_off + qoff);
#pragma unroll
            for (int np = 0; np < 4; np++) {
                const int brow = np * 16 + ((g & 2) << 2) + br_off;
                const uint32_t boff = ((uint32_t)(kc * 32 + ((g & 1) << 4)))
                                    ^ (uint32_t)((brow & 7) << 4);
                const uint32_t rb = (uint32_t)(brow * 128) + boff;
                uint32_t b0, b1, b2, b3;
                LDSM_X4(b0, b1, b2, b3, sKH + rb);
                MMA16816(s[2 * np],     qhf, b0, b1);
                MMA16816(s[2 * np + 1], qhf, b2, b3);
                MMA16816(s[2 * np],     qlf, b0, b1);
                MMA16816(s[2 * np + 1], qlf, b2, b3);
                LDSM_X4(b0, b1, b2, b3, sKL + rb);
                MMA16816(s[2 * np],     qhf, b0, b1);
                MMA16816(s[2 * np + 1], qhf, b2, b3);
            }
        }

        // ---- causal mask ----
        if (k0 + 63 > qrow_w) {
#pragma unroll
            for (int nt = 0; nt < 8; nt++) {
                const int kg0 = k0 + nt * 8 + 2 * (lane & 3);
                if (kg0     > qg0)     s[nt][0] = -1e30f;
                if (kg0 + 1 > qg0)     s[nt][1] = -1e30f;
                if (kg0     > qg0 + 8) s[nt][2] = -1e30f;
                if (kg0 + 1 > qg0 + 8) s[nt][3] = -1e30f;
            }
        }

        // ---- online softmax (base-2) ----
        float rx0 = -1e30f, rx1 = -1e30f;
#pragma unroll
        for (int nt = 0; nt < 8; nt++) {
            rx0 = fmaxf(rx0, fmaxf(s[nt][0], s[nt][1]));
            rx1 = fmaxf(rx1, fmaxf(s[nt][2], s[nt][3]));
        }
        rx0 = fmaxf(rx0, __shfl_xor_sync(0xffffffffu, rx0, 1));
        rx0 = fmaxf(rx0, __shfl_xor_sync(0xffffffffu, rx0, 2));
        rx1 = fmaxf(rx1, __shfl_xor_sync(0xffffffffu, rx1, 1));
        rx1 = fmaxf(rx1, __shfl_xor_sync(0xffffffffu, rx1, 2));
        const float mn0 = fmaxf(m0, rx0);
        const float mn1 = fmaxf(m1, rx1);
        const float sc0 = fexp2(m0 - mn0);
        const float sc1 = fexp2(m1 - mn1);
        m0 = mn0; m1 = mn1;
        l0 *= sc0; l1 *= sc1;
#pragma unroll
        for (int nt = 0; nt < 8; nt++) {
            acc_o[nt][0] *= sc0; acc_o[nt][1] *= sc0;
            acc_o[nt][2] *= sc1; acc_o[nt][3] *= sc1;
        }

        uint32_t ph[4][4], pl[4][4];
#pragma unroll
        for (int nt = 0; nt < 8; nt++) {
            const float p0 = fexp2(s[nt][0] - m0);
            const float p1 = fexp2(s[nt][1] - m0);
            const float p2 = fexp2(s[nt][2] - m1);
            const float p3 = fexp2(s[nt][3] - m1);
            l0 += p0 + p1;
            l1 += p2 + p3;
            const __nv_bfloat16 h0 = __float2bfloat16(p0);
            const __nv_bfloat16 h1 = __float2bfloat16(p1);
            const __nv_bfloat16 h2 = __float2bfloat16(p2);
            const __nv_bfloat16 h3 = __float2bfloat16(p3);
            const int kc = nt >> 1;
            const int rr = (nt & 1) * 2;
            ph[kc][rr]     = packbf2(h0, h1);
            ph[kc][rr + 1] = packbf2(h2, h3);
            pl[kc][rr]     = packbf2(__float2bfloat16(p0 - __bfloat162float(h0)),
                                     __float2bfloat16(p1 - __bfloat162float(h1)));
            pl[kc][rr + 1] = packbf2(__float2bfloat16(p2 - __bfloat162float(h2)),
                                     __float2bfloat16(p3 - __bfloat162float(h3)));
        }

        // ---- O += P V (3-pass hi/lo, ldmatrix.trans for V) ----
#pragma unroll
        for (int kc = 0; kc < 4; kc++) {
#pragma unroll
            for (int np = 0; np < 4; np++) {
                const int vrow = kc * 16 + ((g & 1) << 3) + br_off;
                const uint32_t voff = ((uint32_t)(np * 32 + ((g & 2) << 3)))
                                    ^ (uint32_t)((vrow & 7) << 4);
                const uint32_t rv = (uint32_t)(vrow * 128) + voff;
                uint32_t b0, b1, b2, b3;
                LDSM_X4T(b0, b1, b2, b3, sVH + rv);
                MMA16816(acc_o[2 * np],     ph[kc], b0, b1);
                MMA16816(acc_o[2 * np + 1], ph[kc], b2, b3);
                MMA16816(acc_o[2 * np],     pl[kc], b0, b1);
                MMA16816(acc_o[2 * np + 1], pl[kc], b2, b3);
                LDSM_X4T(b0, b1, b2, b3, sVL + rv);
                MMA16816(acc_o[2 * np],     ph[kc], b0, b1);
                MMA16816(acc_o[2 * np + 1], ph[kc], b2, b3);
            }
        }
        __syncthreads();
    }

    // ---- epilogue: normalize, write stacked bf16 hi/lo rows of g_as ----
    l0 += __shfl_xor_sync(0xffffffffu, l0, 1);
    l0 += __shfl_xor_sync(0xffffffffu, l0, 2);
    l1 += __shfl_xor_sync(0xffffffffu, l1, 1);
    l1 += __shfl_xor_sync(0xffffffffu, l1, 2);
    const float inv0 = 1.0f / l0;
    const float inv1 = 1.0f / l1;

    const size_t row0 = (size_t)(b * SEQ + qg0) * KS;
    const size_t row1 = row0 + 8 * KS;
    const int colbase = h * HD + 2 * (lane & 3);
#pragma unroll
    for (int nt = 0; nt < 8; nt++) {
        const int col = colbase + nt * 8;
        const float v0 = acc_o[nt][0] * inv0;
        const float v1 = acc_o[nt][1] * inv0;
        const float v2 = acc_o[nt][2] * inv1;
        const float v3 = acc_o[nt][3] * inv1;
        const __nv_bfloat16 h0 = __float2bfloat16(v0);
        const __nv_bfloat16 h1 = __float2bfloat16(v1);
        const __nv_bfloat16 h2 = __float2bfloat16(v2);
        const __nv_bfloat16 h3 = __float2bfloat16(v3);
        const uint32_t hi01 = packbf2(h0, h1);
        const uint32_t lo01 = packbf2(__float2bfloat16(v0 - __bfloat162float(h0)),
                                      __float2bfloat16(v1 - __bfloat162float(h1)));
        const uint32_t hi23 = packbf2(h2, h3);
        const uint32_t lo23 = packbf2(__float2bfloat16(v2 - __bfloat162float(h2)),
                                      __float2bfloat16(v3 - __bfloat162float(h3)));
        *(uint32_t*)(outs + row0 + col)        = hi01;
        *(uint32_t*)(outs + row0 + col + 1024) = lo01;
        *(uint32_t*)(outs + row0 + col + 2048) = hi01;
        *(uint32_t*)(outs + row1 + col)        = hi23;
        *(uint32_t*)(outs + row1 + col + 1024) = lo23;
        *(uint32_t*)(outs + row1 + col + 2048) = hi23;
    }
}

// ---------------------------------------------------------------------------
extern "C" void kernel_launch(void* const* d_in, const int* in_sizes, int n_in,
                              void* d_out, int out_size)
{
    const float* x     = (const float*)d_in[0];
    const float* w_qkv = (const float*)d_in[1];
    const float* b_qkv = (const float*)d_in[2];
    const float* w_out = (const float*)d_in[3];
    const float* b_out = (const float*)d_in[4];
    float* out = (float*)d_out;

    __nv_bfloat16 *as, *wqkvs, *wouts, *qh, *ql, *kh, *kl, *vh, *vl;
    cudaGetSymbolAddress((void**)&as,    g_as);
    cudaGetSymbolAddress((void**)&wqkvs, g_wqkv_s);
    cudaGetSymbolAddress((void**)&wouts, g_wout_s);
    cudaGetSymbolAddress((void**)&qh, g_qh);
    cudaGetSymbolAddress((void**)&ql, g_ql);
    cudaGetSymbolAddress((void**)&kh, g_kh);
    cudaGetSymbolAddress((void**)&kl, g_kl);
    cudaGetSymbolAddress((void**)&vh, g_vh);
    cudaGetSymbolAddress((void**)&vl, g_vl);

    cudaFuncSetAttribute(mma_gemm_kernel,
                         cudaFuncAttributeMaxDynamicSharedMemorySize, GEMM_SMEM);
    cudaFuncSetAttribute(attn_mma_kernel,
                         cudaFuncAttributeMaxDynamicSharedMemorySize, ATTN_SMEM);

    // 1) Convert weights (transpose + hi/lo split)
    {
        dim3 grid(QKV_N / 32, HID / 32);
        convert_w_kernel<<<grid, 1024>>>(w_qkv, wqkvs, QKV_N);
    }
    {
        dim3 grid(HID / 32, HID / 32);
        convert_w_kernel<<<grid, 1024>>>(w_out, wouts, HID);
    }
    // 2) Convert x
    convert_act_kernel<<<(MROWS * 1024 + 255) / 256, 256>>>(x, as, MROWS);
    // 3) QKV projection -> head-major bf16 hi/lo Q/K/V (mode 1)
    {
        dim3 grid(QKV_N / BN, MROWS / BM);
        mma_gemm_kernel<<<grid, 256, GEMM_SMEM>>>(as, wqkvs, b_qkv, nullptr,
                                                  MROWS, QKV_N, 1,
                                                  qh, ql, kh, kl, vh, vl);
    }
    // 4) HMMA flash attention (pipelined bf16 feed) -> stacked g_as
    {
        dim3 grid(16, BATCH * NHEADS);
        attn_mma_kernel<<<grid, 256, ATTN_SMEM>>>(qh, ql, kh, kl, vh, vl, as);
    }
    // 5) Output projection (mode 0)
    {
        dim3 grid(HID / BN, MROWS / BM);
        mma_gemm_kernel<<<grid, 256, GEMM_SMEM>>>(as, wouts, b_out, out,
                                                  MROWS, HID, 0,
                                                  nullptr, nullptr, nullptr,
                                                  nullptr, nullptr, nullptr);
    }
}